// round 11
// baseline (speedup 1.0000x reference)
#include <cuda_runtime.h>
#include <cuda_fp16.h>
#include <cstdint>

// ---------------------------------------------------------------------------
// GCN_VCG, round 11:
//  - update2 restored to 2 CTAs/SM (230.4KB < 228KB*... fits per R9 evidence).
//  - prep fused: 1 zero kernel, 1 weight-conversion kernel.
//  Same math as R9/R10 (fp16 single-pass mma.sync, fp16 intermediates, CSR).
// ---------------------------------------------------------------------------

#define D        128
#define NT       256
#define VMAX     50000
#define CMAX     210000
#define EHMAX    315000

// ------------------------- scratch (no runtime alloc) ----------------------
__device__ unsigned short g_t_pv2c[(size_t)VMAX * D];
__device__ unsigned short g_t_nv2c[(size_t)VMAX * D];
__device__ unsigned short g_t_pc2v[(size_t)CMAX * D];
__device__ unsigned short g_t_nc2v[(size_t)CMAX * D];
__device__ unsigned short g_agg_c[2][(size_t)CMAX * D];
__device__ unsigned short g_agg_v[2][(size_t)VMAX * D];
__device__ unsigned char g_wimg_mlp[4][2 * 32768];
__device__ unsigned char g_wimg_cu[3 * 32768];
__device__ unsigned char g_wimg_vu[3 * 32768];
__device__ int   g_degi_pv[VMAX], g_degi_nv[VMAX];
__device__ int   g_degi_pc[CMAX], g_degi_nc[CMAX];
__device__ int   g_rp_pc[CMAX + 1], g_rp_nc[CMAX + 1];
__device__ int   g_rp_pv[VMAX + 1], g_rp_nv[VMAX + 1];
__device__ int   g_fl_pc[CMAX], g_fl_nc[CMAX], g_fl_pv[VMAX], g_fl_nv[VMAX];
__device__ int   g_sl_pc_src[EHMAX], g_sl_nc_src[EHMAX];
__device__ int   g_sl_pv_src[EHMAX], g_sl_nv_src[EHMAX];
__device__ float g_sl_pc_w[EHMAX], g_sl_nc_w[EHMAX];
__device__ float g_sl_pv_w[EHMAX], g_sl_nv_w[EHMAX];

// ------------------------------ helpers ------------------------------------
__device__ __forceinline__ uint32_t smem_u32(const void* p) {
    uint32_t a;
    asm("{ .reg .u64 t; cvta.to.shared.u64 t, %1; cvt.u32.u64 %0, t; }"
        : "=r"(a) : "l"(p));
    return a;
}

__device__ __host__ __forceinline__ uint32_t swz(int r, int c) {
    return ((uint32_t)r << 8) + ((uint32_t)(((c >> 3) ^ (r & 7)) & 15) << 4)
         + ((uint32_t)(c & 7) << 1);
}

__device__ __forceinline__ uint32_t pack_h2(float a, float b) {
    __half2 h = __floats2half2_rn(a, b);
    return *reinterpret_cast<uint32_t*>(&h);
}

__device__ __forceinline__ float2 unpack_h2(uint32_t u) {
    return __half22float2(*reinterpret_cast<__half2*>(&u));
}

__device__ __forceinline__ void ldm4(uint32_t addr, uint32_t& d0, uint32_t& d1,
                                     uint32_t& d2, uint32_t& d3) {
    asm volatile("ldmatrix.sync.aligned.m8n8.x4.shared.b16 {%0,%1,%2,%3}, [%4];"
                 : "=r"(d0), "=r"(d1), "=r"(d2), "=r"(d3) : "r"(addr));
}

__device__ __forceinline__ void mma16816(float* c, const uint32_t* a,
                                         const uint32_t* b) {
    asm volatile(
        "mma.sync.aligned.m16n8k16.row.col.f32.f16.f16.f32 "
        "{%0,%1,%2,%3}, {%4,%5,%6,%7}, {%8,%9}, {%0,%1,%2,%3};"
        : "+f"(c[0]), "+f"(c[1]), "+f"(c[2]), "+f"(c[3])
        : "r"(a[0]), "r"(a[1]), "r"(a[2]), "r"(a[3]), "r"(b[0]), "r"(b[1]));
}

__device__ __forceinline__ void cp16(uint32_t saddr, const void* g, bool pred) {
    int sz = pred ? 16 : 0;
    asm volatile("cp.async.cg.shared.global [%0], [%1], 16, %2;"
                 :: "r"(saddr), "l"(g), "r"(sz));
}
#define CP_COMMIT() asm volatile("cp.async.commit_group;" ::: "memory")
#define CP_WAIT0()  asm volatile("cp.async.wait_group 0;" ::: "memory")

__device__ __forceinline__ void gemm_pass64(uint32_t sA, uint32_t sW,
                                            float acc[2][4][4],
                                            int wm, int wn, int lane) {
#pragma unroll
    for (int ks = 0; ks < 8; ks++) {
        const int kc = ks * 2;
        uint32_t a[2][4];
#pragma unroll
        for (int s = 0; s < 2; s++) {
            int row = wm * 32 + s * 16 + (lane & 7) + ((lane >> 3) & 1) * 8;
            int chunk = ((kc + (lane >> 4)) ^ (row & 7)) & 15;
            ldm4(sA + row * 256 + chunk * 16, a[s][0], a[s][1], a[s][2], a[s][3]);
        }
        uint32_t b[4][2];
#pragma unroll
        for (int p = 0; p < 2; p++) {
            int row = wn * 32 + p * 16 + (lane & 7) + (lane >> 4) * 8;
            int chunk = ((kc + ((lane >> 3) & 1)) ^ (row & 7)) & 15;
            ldm4(sW + row * 256 + chunk * 16,
                 b[2 * p][0], b[2 * p][1], b[2 * p + 1][0], b[2 * p + 1][1]);
        }
#pragma unroll
        for (int s = 0; s < 2; s++)
#pragma unroll
            for (int nt = 0; nt < 4; nt++)
                mma16816(acc[s][nt], a[s], b[nt]);
    }
}

__device__ __forceinline__ void zero_acc(float acc[2][4][4]) {
#pragma unroll
    for (int s = 0; s < 2; s++)
#pragma unroll
        for (int nt = 0; nt < 4; nt++)
#pragma unroll
            for (int j = 0; j < 4; j++) acc[s][nt][j] = 0.f;
}

__device__ __forceinline__ void load64_f32(const float* __restrict__ X,
                                           char* sm, uint32_t sa,
                                           int row0, int N, int tid) {
#pragma unroll
    for (int i = tid; i < 2048; i += NT) {
        int r = i >> 5, c4 = i & 31, g = row0 + r;
        float4 x = make_float4(0.f, 0.f, 0.f, 0.f);
        if (g < N) x = *reinterpret_cast<const float4*>(X + (size_t)g * D + c4 * 4);
        uint2 h = make_uint2(pack_h2(x.x, x.y), pack_h2(x.z, x.w));
        *reinterpret_cast<uint2*>(sm + sa + swz(r, c4 * 4)) = h;
    }
}

__device__ __forceinline__ void load64_f16(const unsigned short* __restrict__ X,
                                           char* sm, uint32_t sa,
                                           int row0, int N, int tid) {
#pragma unroll
    for (int i = tid; i < 2048; i += NT) {
        int r = i >> 5, c4 = i & 31, g = row0 + r;
        uint2 h = make_uint2(0u, 0u);
        if (g < N) h = *reinterpret_cast<const uint2*>(X + (size_t)g * D + c4 * 4);
        *reinterpret_cast<uint2*>(sm + sa + swz(r, c4 * 4)) = h;
    }
}

// --------------------------- fused MLP kernel -------------------------------
#define MS_W    0
#define MS_A    65536
#define MS_B    81920
#define MS_TOT  82944

extern "C" __global__ void __launch_bounds__(NT, 2)
mlp4_kernel(const float* __restrict__ vin, const float* __restrict__ cin,
            const uint4* __restrict__ img,
            const float* __restrict__ b0, const float* __restrict__ b1,
            const float* __restrict__ b2, const float* __restrict__ b3,
            unsigned short* __restrict__ y0, unsigned short* __restrict__ y1,
            unsigned short* __restrict__ y2, unsigned short* __restrict__ y3,
            int V, int C) {
    extern __shared__ char sm[];
    const uint32_t sb = smem_u32(sm);
    const int tid = threadIdx.x, wid = tid >> 5, lane = tid & 31;
    const int wm = wid >> 2, wn = wid & 3;
    float* bs = reinterpret_cast<float*>(sm + MS_B);

    const int tV = (V + 63) >> 6, tC = (C + 63) >> 6;
    const long T = 2L * tV + 2L * tC;
    const int G = gridDim.x;
    int cV = (int)((long)G * tV / T); if (cV < 1) cV = 1;
    int cC = (G - 2 * cV) >> 1; if (cC < 1) cC = 1;
    const int bnd1 = cV, bnd2 = 2 * cV, bnd3 = 2 * cV + cC;

    int seg, start, stride, tiles, N;
    const float* X; const float* bias; unsigned short* Y;
    const int b = blockIdx.x;
    if (b < bnd1)      { seg = 0; start = b;        stride = cV;     }
    else if (b < bnd2) { seg = 1; start = b - bnd1; stride = cV;     }
    else if (b < bnd3) { seg = 2; start = b - bnd2; stride = cC;     }
    else               { seg = 3; start = b - bnd3; stride = G - bnd3; }
    if (seg < 2) { X = vin; N = V; tiles = tV; }
    else         { X = cin; N = C; tiles = tC; }
    bias = (seg == 0) ? b0 : (seg == 1) ? b1 : (seg == 2) ? b2 : b3;
    Y    = (seg == 0) ? y0 : (seg == 1) ? y1 : (seg == 2) ? y2 : y3;
    const uint4* Wimg = img + (size_t)seg * 4096;

#pragma unroll 4
    for (int i = tid; i < 4096; i += NT)
        cp16(sb + MS_W + i * 16, Wimg + i, true);
    if (tid < 2 * D) bs[tid] = bias[tid];
    CP_COMMIT();
    CP_WAIT0();
    __syncthreads();

    for (int t = start; t < tiles; t += stride) {
        const int row0 = t * 64;
        load64_f32(X, sm, MS_A, row0, N, tid);
        __syncthreads();

        float acc[2][4][4];
        zero_acc(acc);
        gemm_pass64(sb + MS_A, sb + MS_W, acc, wm, wn, lane);
        __syncthreads();

#pragma unroll
        for (int s = 0; s < 2; s++) {
#pragma unroll
            for (int nt = 0; nt < 4; nt++) {
                int m = wm * 32 + s * 16 + (lane >> 2);
                int n = wn * 32 + nt * 8 + (lane & 3) * 2;
                float c0 = bs[n], c1 = bs[n + 1];
                uint32_t h0 = pack_h2(fmaxf(acc[s][nt][0] + c0, 0.f),
                                      fmaxf(acc[s][nt][1] + c1, 0.f));
                uint32_t h1 = pack_h2(fmaxf(acc[s][nt][2] + c0, 0.f),
                                      fmaxf(acc[s][nt][3] + c1, 0.f));
                *reinterpret_cast<uint32_t*>(sm + MS_A + swz(m, n)) = h0;
                *reinterpret_cast<uint32_t*>(sm + MS_A + swz(m + 8, n)) = h1;
            }
        }
        __syncthreads();

        zero_acc(acc);
        gemm_pass64(sb + MS_A, sb + MS_W + 32768, acc, wm, wn, lane);

#pragma unroll
        for (int s = 0; s < 2; s++) {
#pragma unroll
            for (int nt = 0; nt < 4; nt++) {
                int m = wm * 32 + s * 16 + (lane >> 2);
                int n = wn * 32 + nt * 8 + (lane & 3) * 2;
                float c0 = bs[D + n], c1 = bs[D + n + 1];
                int g0 = row0 + m, g1 = row0 + m + 8;
                if (g0 < N)
                    *reinterpret_cast<uint32_t*>(Y + (size_t)g0 * D + n) =
                        pack_h2(acc[s][nt][0] + c0, acc[s][nt][1] + c1);
                if (g1 < N)
                    *reinterpret_cast<uint32_t*>(Y + (size_t)g1 * D + n) =
                        pack_h2(acc[s][nt][2] + c0, acc[s][nt][3] + c1);
            }
        }
        __syncthreads();
    }
}

// --------------------------- fused update kernel ----------------------------
// 2 CTAs/SM: 2 x 115200 = 230400 B fits in 228KB smem/SM.
#define US_W    0
#define US_A    98304
#define US_B    114688
#define US_TOT  115200

extern "C" __global__ void __launch_bounds__(NT, 2)
update2_kernel(const float* __restrict__ cin, const float* __restrict__ vin,
               const unsigned short* __restrict__ aggc_p,
               const unsigned short* __restrict__ aggc_n,
               const unsigned short* __restrict__ aggv_p,
               const unsigned short* __restrict__ aggv_n,
               const uint4* __restrict__ cuImg, const uint4* __restrict__ vuImg,
               const float* __restrict__ cub, const float* __restrict__ vub,
               float* __restrict__ cout, float* __restrict__ vout,
               int V, int C) {
    extern __shared__ char sm[];
    const uint32_t sb = smem_u32(sm);
    const int tid = threadIdx.x, wid = tid >> 5, lane = tid & 31;
    const int wm = wid >> 2, wn = wid & 3;
    float* bs = reinterpret_cast<float*>(sm + US_B);

    const int tV = (V + 63) >> 6, tC = (C + 63) >> 6;
    const int G = gridDim.x;
    int cC = (int)((long)G * tC / (tC + tV)); if (cC < 1) cC = 1;
    if (cC > G - 1) cC = G - 1;

    int start, stride, tiles, N;
    const float* X0; const unsigned short *X1, *X2;
    const uint4* Wimg; const float* bias; float* Y;
    const int b = blockIdx.x;
    if (b < cC) {
        start = b; stride = cC; tiles = tC; N = C;
        X0 = cin; X1 = aggc_p; X2 = aggc_n;
        Wimg = cuImg; bias = cub; Y = cout;
    } else {
        start = b - cC; stride = G - cC; tiles = tV; N = V;
        X0 = vin; X1 = aggv_p; X2 = aggv_n;
        Wimg = vuImg; bias = vub; Y = vout;
    }

#pragma unroll 4
    for (int i = tid; i < 6144; i += NT)
        cp16(sb + US_W + i * 16, Wimg + i, true);
    if (tid < D) bs[tid] = bias[tid];
    CP_COMMIT();
    CP_WAIT0();
    __syncthreads();

    for (int t = start; t < tiles; t += stride) {
        const int row0 = t * 64;
        float acc[2][4][4];
        zero_acc(acc);

        load64_f32(X0, sm, US_A, row0, N, tid);
        __syncthreads();
        gemm_pass64(sb + US_A, sb + US_W, acc, wm, wn, lane);
        __syncthreads();

        load64_f16(X1, sm, US_A, row0, N, tid);
        __syncthreads();
        gemm_pass64(sb + US_A, sb + US_W + 32768, acc, wm, wn, lane);
        __syncthreads();

        load64_f16(X2, sm, US_A, row0, N, tid);
        __syncthreads();
        gemm_pass64(sb + US_A, sb + US_W + 65536, acc, wm, wn, lane);
        __syncthreads();

#pragma unroll
        for (int s = 0; s < 2; s++) {
#pragma unroll
            for (int nt = 0; nt < 4; nt++) {
                int m = wm * 32 + s * 16 + (lane >> 2);
                int n = wn * 32 + nt * 8 + (lane & 3) * 2;
                float c0 = bs[n], c1 = bs[n + 1];
                int g0 = row0 + m, g1 = row0 + m + 8;
                if (g0 < N) {
                    float2 o = make_float2(acc[s][nt][0] + c0, acc[s][nt][1] + c1);
                    *reinterpret_cast<float2*>(Y + (size_t)g0 * D + n) = o;
                }
                if (g1 < N) {
                    float2 o = make_float2(acc[s][nt][2] + c0, acc[s][nt][3] + c1);
                    *reinterpret_cast<float2*>(Y + (size_t)g1 * D + n) = o;
                }
            }
        }
    }
}

// ----------------------- fused weight conversion ----------------------------
// one kernel converts all 10 images: 4 mlp (2 layers each) + 3 cu + 3 vu
extern "C" __global__ void wconv_all_kernel(
    const float* __restrict__ W0, const float* __restrict__ W1,
    const float* __restrict__ W2, const float* __restrict__ W3,
    const float* __restrict__ cuW, const float* __restrict__ vuW) {
    int t = blockIdx.x * blockDim.x + threadIdx.x;
    const int MLP_TOT = 4 * 2 * 128 * 128;   // 131072
    const int UPD_TOT = 384 * 128;           // 49152
    if (t < MLP_TOT) {
        int w = t >> 15, rest = t & 32767;
        int l = rest >> 14, k = (rest >> 7) & 127, n = rest & 127;
        const float* W = (w == 0) ? W0 : (w == 1) ? W1 : (w == 2) ? W2 : W3;
        __half h = __float2half_rn(W[rest]);
        *reinterpret_cast<__half*>(g_wimg_mlp[w] + (size_t)l * 32768 + swz(n, k)) = h;
    } else if (t < MLP_TOT + UPD_TOT) {
        int u = t - MLP_TOT;
        int k = u >> 7, n = u & 127;
        int s = k >> 7, kl = k & 127;
        __half h = __float2half_rn(cuW[u]);
        *reinterpret_cast<__half*>(g_wimg_cu + (size_t)s * 32768 + swz(n, kl)) = h;
    } else if (t < MLP_TOT + 2 * UPD_TOT) {
        int u = t - MLP_TOT - UPD_TOT;
        int k = u >> 7, n = u & 127;
        int s = k >> 7, kl = k & 127;
        __half h = __float2half_rn(vuW[u]);
        *reinterpret_cast<__half*>(g_wimg_vu + (size_t)s * 32768 + swz(n, kl)) = h;
    }
}

// ----------------------------- fused zero prep ------------------------------
extern "C" __global__ void zero_prep_kernel(int V, int C) {
    int t = blockIdx.x * blockDim.x + threadIdx.x;
    if (t < V) {
        g_degi_pv[t] = 0; g_degi_nv[t] = 0;
        g_fl_pv[t] = 0;   g_fl_nv[t] = 0;
    }
    if (t < C) {
        g_degi_pc[t] = 0; g_degi_nc[t] = 0;
        g_fl_pc[t] = 0;   g_fl_nc[t] = 0;
    }
}

// ------------------------------ CSR build -----------------------------------
extern "C" __global__ void degree_kernel(const int* __restrict__ vE,
                                         const int* __restrict__ cE,
                                         const int* __restrict__ pE,
                                         const int* __restrict__ nE, int Eh) {
    int t = blockIdx.x * blockDim.x + threadIdx.x;
    if (t < Eh) {
        int e = pE[t];
        atomicAdd(&g_degi_pv[vE[e]], 1);
        atomicAdd(&g_degi_pc[cE[e]], 1);
    } else if (t < 2 * Eh) {
        int e = nE[t - Eh];
        atomicAdd(&g_degi_nv[vE[e]], 1);
        atomicAdd(&g_degi_nc[cE[e]], 1);
    }
}

extern "C" __global__ void __launch_bounds__(1024)
scan4_kernel(int V, int C) {
    const int* d; int* r; int n;
    switch (blockIdx.x) {
        case 0:  d = g_degi_pc; r = g_rp_pc; n = C; break;
        case 1:  d = g_degi_nc; r = g_rp_nc; n = C; break;
        case 2:  d = g_degi_pv; r = g_rp_pv; n = V; break;
        default: d = g_degi_nv; r = g_rp_nv; n = V; break;
    }
    __shared__ int wsum[32];
    __shared__ int sh_carry, sh_total;
    int tid = threadIdx.x, lane = tid & 31, wid = tid >> 5;
    if (tid == 0) sh_carry = 0;
    __syncthreads();
    for (int base = 0; base < n; base += 1024) {
        int i = base + tid;
        int v = (i < n) ? d[i] : 0;
        int incl = v;
#pragma unroll
        for (int o = 1; o < 32; o <<= 1) {
            int x = __shfl_up_sync(0xffffffffu, incl, o);
            if (lane >= o) incl += x;
        }
        if (lane == 31) wsum[wid] = incl;
        __syncthreads();
        if (tid < 32) {
            int s = wsum[tid], ip = s;
#pragma unroll
            for (int o = 1; o < 32; o <<= 1) {
                int x = __shfl_up_sync(0xffffffffu, ip, o);
                if (tid >= o) ip += x;
            }
            wsum[tid] = ip - s;
            if (tid == 31) sh_total = ip;
        }
        __syncthreads();
        if (i < n) r[i] = sh_carry + wsum[wid] + incl - v;
        __syncthreads();
        if (tid == 0) sh_carry += sh_total;
        __syncthreads();
    }
    if (tid == 0) r[n] = sh_carry;
}

extern "C" __global__ void fill_kernel(const int* __restrict__ vE,
                                       const int* __restrict__ cE,
                                       const int* __restrict__ pE,
                                       const int* __restrict__ nE, int Eh) {
    int t = blockIdx.x * blockDim.x + threadIdx.x;
    if (t < Eh) {
        int e = pE[t];
        int v = vE[e], c = cE[e];
        float inv = rsqrtf((float)max(g_degi_pv[v], 1) * (float)max(g_degi_pc[c], 1));
        int pos = g_rp_pc[c] + atomicAdd(&g_fl_pc[c], 1);
        g_sl_pc_src[pos] = v;
        g_sl_pc_w[pos] = inv;
        int pos2 = g_rp_pv[v] + atomicAdd(&g_fl_pv[v], 1);
        g_sl_pv_src[pos2] = c;
        g_sl_pv_w[pos2] = inv;
    } else if (t < 2 * Eh) {
        int e = nE[t - Eh];
        int v = vE[e], c = cE[e];
        float inv = rsqrtf((float)max(g_degi_nv[v], 1) * (float)max(g_degi_nc[c], 1));
        int pos = g_rp_nc[c] + atomicAdd(&g_fl_nc[c], 1);
        g_sl_nc_src[pos] = v;
        g_sl_nc_w[pos] = inv;
        int pos2 = g_rp_nv[v] + atomicAdd(&g_fl_nv[v], 1);
        g_sl_nv_src[pos2] = c;
        g_sl_nv_w[pos2] = inv;
    }
}

// ------------------------- fused CSR gather (x4) ----------------------------
extern "C" __global__ void __launch_bounds__(NT)
gather4_kernel(const unsigned short* __restrict__ t_pv2c,
               const unsigned short* __restrict__ t_nv2c,
               const unsigned short* __restrict__ t_pc2v,
               const unsigned short* __restrict__ t_nc2v,
               unsigned short* __restrict__ aggc_p,
               unsigned short* __restrict__ aggc_n,
               unsigned short* __restrict__ aggv_p,
               unsigned short* __restrict__ aggv_n,
               int V, int C) {
    long t = (long)blockIdx.x * blockDim.x + threadIdx.x;
    int gidx = (int)(t >> 4), sub = (int)(t & 15);
    const unsigned short* src; unsigned short* dst;
    const int* rp; const int* sl; const float* wv;
    int node;
    if (gidx < C) {
        node = gidx; src = t_pv2c; dst = aggc_p;
        rp = g_rp_pc; sl = g_sl_pc_src; wv = g_sl_pc_w;
    } else if (gidx < 2 * C) {
        node = gidx - C; src = t_nv2c; dst = aggc_n;
        rp = g_rp_nc; sl = g_sl_nc_src; wv = g_sl_nc_w;
    } else if (gidx < 2 * C + V) {
        node = gidx - 2 * C; src = t_pc2v; dst = aggv_p;
        rp = g_rp_pv; sl = g_sl_pv_src; wv = g_sl_pv_w;
    } else if (gidx < 2 * C + 2 * V) {
        node = gidx - 2 * C - V; src = t_nc2v; dst = aggv_n;
        rp = g_rp_nv; sl = g_sl_nv_src; wv = g_sl_nv_w;
    } else return;

    int j = rp[node], end = rp[node + 1];
    float acc[8] = {0.f, 0.f, 0.f, 0.f, 0.f, 0.f, 0.f, 0.f};
    int s_next = 0; float w_next = 0.f;
    if (j < end) { s_next = __ldg(sl + j); w_next = __ldg(wv + j); }
    while (j < end) {
        int s = s_next; float w = w_next;
        j++;
        if (j < end) { s_next = __ldg(sl + j); w_next = __ldg(wv + j); }
        uint4 x = __ldg(reinterpret_cast<const uint4*>(src + (size_t)s * D) + sub);
        float2 f0 = unpack_h2(x.x), f1 = unpack_h2(x.y);
        float2 f2 = unpack_h2(x.z), f3 = unpack_h2(x.w);
        acc[0] = fmaf(w, f0.x, acc[0]); acc[1] = fmaf(w, f0.y, acc[1]);
        acc[2] = fmaf(w, f1.x, acc[2]); acc[3] = fmaf(w, f1.y, acc[3]);
        acc[4] = fmaf(w, f2.x, acc[4]); acc[5] = fmaf(w, f2.y, acc[5]);
        acc[6] = fmaf(w, f3.x, acc[6]); acc[7] = fmaf(w, f3.y, acc[7]);
    }
    uint4 o;
    o.x = pack_h2(acc[0], acc[1]);
    o.y = pack_h2(acc[2], acc[3]);
    o.z = pack_h2(acc[4], acc[5]);
    o.w = pack_h2(acc[6], acc[7]);
    reinterpret_cast<uint4*>(dst + (size_t)node * D)[sub] = o;
}

// -------------------------------- launch ------------------------------------
extern "C" void kernel_launch(void* const* d_in, const int* in_sizes, int n_in,
                              void* d_out, int out_size) {
    int base = (n_in >= 20) ? 2 : 0;
    const int*   v_edge = (const int*)d_in[base + 0];
    const int*   c_edge = (const int*)d_in[base + 1];
    const int*   p_edge = (const int*)d_in[base + 2];
    const int*   n_edge = (const int*)d_in[base + 3];
    const float* v0     = (const float*)d_in[base + 4];
    const float* c0     = (const float*)d_in[base + 5];
    const float *Wm[4], *Bm[4];
    for (int i = 0; i < 4; i++) {
        Wm[i] = (const float*)d_in[base + 6 + 2 * i];
        Bm[i] = (const float*)d_in[base + 7 + 2 * i];
    }
    const float* cuW = (const float*)d_in[base + 14];
    const float* cub = (const float*)d_in[base + 15];
    const float* vuW = (const float*)d_in[base + 16];
    const float* vub = (const float*)d_in[base + 17];

    const int Eh = in_sizes[base + 2];
    const int V  = in_sizes[base + 4] / D;
    const int C  = in_sizes[base + 5] / D;

    void* p;
    unsigned short *t_pv2c, *t_nv2c, *t_pc2v, *t_nc2v, *agg_c, *agg_v;
    unsigned char *img_mlp, *img_cu, *img_vu;
    cudaGetSymbolAddress(&p, g_t_pv2c); t_pv2c = (unsigned short*)p;
    cudaGetSymbolAddress(&p, g_t_nv2c); t_nv2c = (unsigned short*)p;
    cudaGetSymbolAddress(&p, g_t_pc2v); t_pc2v = (unsigned short*)p;
    cudaGetSymbolAddress(&p, g_t_nc2v); t_nc2v = (unsigned short*)p;
    cudaGetSymbolAddress(&p, g_agg_c);  agg_c  = (unsigned short*)p;
    cudaGetSymbolAddress(&p, g_agg_v);  agg_v  = (unsigned short*)p;
    cudaGetSymbolAddress(&p, g_wimg_mlp); img_mlp = (unsigned char*)p;
    cudaGetSymbolAddress(&p, g_wimg_cu);  img_cu  = (unsigned char*)p;
    cudaGetSymbolAddress(&p, g_wimg_vu);  img_vu  = (unsigned char*)p;

    unsigned short* agg_c_p = agg_c;
    unsigned short* agg_c_n = agg_c + (size_t)CMAX * D;
    unsigned short* agg_v_p = agg_v;
    unsigned short* agg_v_n = agg_v + (size_t)VMAX * D;

    float* outv = (float*)d_out;
    float* outc = outv + (size_t)4 * V * D;

    int sms = 148;
    cudaDeviceGetAttribute(&sms, cudaDevAttrMultiProcessorCount, 0);

    cudaFuncSetAttribute(mlp4_kernel,
                         cudaFuncAttributeMaxDynamicSharedMemorySize, MS_TOT);
    cudaFuncSetAttribute(update2_kernel,
                         cudaFuncAttributeMaxDynamicSharedMemorySize, US_TOT);

    // ---- prep: zero -> degrees -> scan -> fill; fused wconv ----
    {
        int mx = (V > C) ? V : C;
        zero_prep_kernel<<<(mx + NT - 1) / NT, NT>>>(V, C);
        int blk = (2 * Eh + NT - 1) / NT;
        degree_kernel<<<blk, NT>>>(v_edge, c_edge, p_edge, n_edge, Eh);
        scan4_kernel<<<4, 1024>>>(V, C);
        fill_kernel<<<blk, NT>>>(v_edge, c_edge, p_edge, n_edge, Eh);
        const int wtot = 4 * 2 * 128 * 128 + 2 * 384 * 128;
        wconv_all_kernel<<<(wtot + NT - 1) / NT, NT>>>(
            Wm[0], Wm[1], Wm[2], Wm[3], cuW, vuW);
    }

    cudaMemcpyAsync(outv, v0, (size_t)V * D * sizeof(float), cudaMemcpyDeviceToDevice);
    cudaMemcpyAsync(outc, c0, (size_t)C * D * sizeof(float), cudaMemcpyDeviceToDevice);

    const long ggroups = 2L * C + 2L * V;
    const int gblocks = (int)((ggroups * 16 + NT - 1) / NT);

    for (int t = 0; t < 3; t++) {
        const float* vin = outv + (size_t)t * V * D;
        const float* cin = outc + (size_t)t * C * D;
        float* vout = outv + (size_t)(t + 1) * V * D;
        float* cout = outc + (size_t)(t + 1) * C * D;

        mlp4_kernel<<<2 * sms, NT, MS_TOT>>>(
            vin, cin, (const uint4*)img_mlp,
            Bm[0], Bm[1], Bm[2], Bm[3],
            t_pv2c, t_nv2c, t_pc2v, t_nc2v, V, C);

        gather4_kernel<<<gblocks, NT>>>(
            t_pv2c, t_nv2c, t_pc2v, t_nc2v,
            agg_c_p, agg_c_n, agg_v_p, agg_v_n, V, C);

        update2_kernel<<<2 * sms, NT, US_TOT>>>(
            cin, vin, agg_c_p, agg_c_n, agg_v_p, agg_v_n,
            (const uint4*)img_cu, (const uint4*)img_vu,
            cub, vub, cout, vout, V, C);
    }
}

// round 12
// speedup vs baseline: 1.4049x; 1.4049x over previous
#include <cuda_runtime.h>
#include <cuda_fp16.h>
#include <cstdint>

// ---------------------------------------------------------------------------
// GCN_VCG, round 12: R10 skeleton (best) + update2 cp.async A1/A2 prefetch.
//  - mlp4: fused 4-segment MLP kernel, 2 CTAs/SM (unchanged from R10).
//  - update2: (NT,1)/grid=sms as R10, but X1/X2 fp16 tiles streamed via
//    cp.async into separate A-buffers while X0 converts -> 1 serial load phase.
//  - gather4 fused; prep fused (zero_prep + wconv_all).
// ---------------------------------------------------------------------------

#define D        128
#define NT       256
#define VMAX     50000
#define CMAX     210000
#define EHMAX    315000

// ------------------------- scratch (no runtime alloc) ----------------------
__device__ unsigned short g_t_pv2c[(size_t)VMAX * D];
__device__ unsigned short g_t_nv2c[(size_t)VMAX * D];
__device__ unsigned short g_t_pc2v[(size_t)CMAX * D];
__device__ unsigned short g_t_nc2v[(size_t)CMAX * D];
__device__ unsigned short g_agg_c[2][(size_t)CMAX * D];
__device__ unsigned short g_agg_v[2][(size_t)VMAX * D];
__device__ unsigned char g_wimg_mlp[4][2 * 32768];
__device__ unsigned char g_wimg_cu[3 * 32768];
__device__ unsigned char g_wimg_vu[3 * 32768];
__device__ int   g_degi_pv[VMAX], g_degi_nv[VMAX];
__device__ int   g_degi_pc[CMAX], g_degi_nc[CMAX];
__device__ int   g_rp_pc[CMAX + 1], g_rp_nc[CMAX + 1];
__device__ int   g_rp_pv[VMAX + 1], g_rp_nv[VMAX + 1];
__device__ int   g_fl_pc[CMAX], g_fl_nc[CMAX], g_fl_pv[VMAX], g_fl_nv[VMAX];
__device__ int   g_sl_pc_src[EHMAX], g_sl_nc_src[EHMAX];
__device__ int   g_sl_pv_src[EHMAX], g_sl_nv_src[EHMAX];
__device__ float g_sl_pc_w[EHMAX], g_sl_nc_w[EHMAX];
__device__ float g_sl_pv_w[EHMAX], g_sl_nv_w[EHMAX];

// ------------------------------ helpers ------------------------------------
__device__ __forceinline__ uint32_t smem_u32(const void* p) {
    uint32_t a;
    asm("{ .reg .u64 t; cvta.to.shared.u64 t, %1; cvt.u32.u64 %0, t; }"
        : "=r"(a) : "l"(p));
    return a;
}

__device__ __host__ __forceinline__ uint32_t swz(int r, int c) {
    return ((uint32_t)r << 8) + ((uint32_t)(((c >> 3) ^ (r & 7)) & 15) << 4)
         + ((uint32_t)(c & 7) << 1);
}

__device__ __forceinline__ uint32_t pack_h2(float a, float b) {
    __half2 h = __floats2half2_rn(a, b);
    return *reinterpret_cast<uint32_t*>(&h);
}

__device__ __forceinline__ float2 unpack_h2(uint32_t u) {
    return __half22float2(*reinterpret_cast<__half2*>(&u));
}

__device__ __forceinline__ void ldm4(uint32_t addr, uint32_t& d0, uint32_t& d1,
                                     uint32_t& d2, uint32_t& d3) {
    asm volatile("ldmatrix.sync.aligned.m8n8.x4.shared.b16 {%0,%1,%2,%3}, [%4];"
                 : "=r"(d0), "=r"(d1), "=r"(d2), "=r"(d3) : "r"(addr));
}

__device__ __forceinline__ void mma16816(float* c, const uint32_t* a,
                                         const uint32_t* b) {
    asm volatile(
        "mma.sync.aligned.m16n8k16.row.col.f32.f16.f16.f32 "
        "{%0,%1,%2,%3}, {%4,%5,%6,%7}, {%8,%9}, {%0,%1,%2,%3};"
        : "+f"(c[0]), "+f"(c[1]), "+f"(c[2]), "+f"(c[3])
        : "r"(a[0]), "r"(a[1]), "r"(a[2]), "r"(a[3]), "r"(b[0]), "r"(b[1]));
}

__device__ __forceinline__ void cp16(uint32_t saddr, const void* g, bool pred) {
    int sz = pred ? 16 : 0;
    asm volatile("cp.async.cg.shared.global [%0], [%1], 16, %2;"
                 :: "r"(saddr), "l"(g), "r"(sz));
}
#define CP_COMMIT() asm volatile("cp.async.commit_group;" ::: "memory")
#define CP_WAIT0()  asm volatile("cp.async.wait_group 0;" ::: "memory")

__device__ __forceinline__ void gemm_pass64(uint32_t sA, uint32_t sW,
                                            float acc[2][4][4],
                                            int wm, int wn, int lane) {
#pragma unroll
    for (int ks = 0; ks < 8; ks++) {
        const int kc = ks * 2;
        uint32_t a[2][4];
#pragma unroll
        for (int s = 0; s < 2; s++) {
            int row = wm * 32 + s * 16 + (lane & 7) + ((lane >> 3) & 1) * 8;
            int chunk = ((kc + (lane >> 4)) ^ (row & 7)) & 15;
            ldm4(sA + row * 256 + chunk * 16, a[s][0], a[s][1], a[s][2], a[s][3]);
        }
        uint32_t b[4][2];
#pragma unroll
        for (int p = 0; p < 2; p++) {
            int row = wn * 32 + p * 16 + (lane & 7) + (lane >> 4) * 8;
            int chunk = ((kc + ((lane >> 3) & 1)) ^ (row & 7)) & 15;
            ldm4(sW + row * 256 + chunk * 16,
                 b[2 * p][0], b[2 * p][1], b[2 * p + 1][0], b[2 * p + 1][1]);
        }
#pragma unroll
        for (int s = 0; s < 2; s++)
#pragma unroll
            for (int nt = 0; nt < 4; nt++)
                mma16816(acc[s][nt], a[s], b[nt]);
    }
}

__device__ __forceinline__ void zero_acc(float acc[2][4][4]) {
#pragma unroll
    for (int s = 0; s < 2; s++)
#pragma unroll
        for (int nt = 0; nt < 4; nt++)
#pragma unroll
            for (int j = 0; j < 4; j++) acc[s][nt][j] = 0.f;
}

__device__ __forceinline__ void load64_f32(const float* __restrict__ X,
                                           char* sm, uint32_t sa,
                                           int row0, int N, int tid) {
#pragma unroll
    for (int i = tid; i < 2048; i += NT) {
        int r = i >> 5, c4 = i & 31, g = row0 + r;
        float4 x = make_float4(0.f, 0.f, 0.f, 0.f);
        if (g < N) x = *reinterpret_cast<const float4*>(X + (size_t)g * D + c4 * 4);
        uint2 h = make_uint2(pack_h2(x.x, x.y), pack_h2(x.z, x.w));
        *reinterpret_cast<uint2*>(sm + sa + swz(r, c4 * 4)) = h;
    }
}

// cp.async a 64-row fp16 tile into a swizzled A buffer (16B chunk granularity)
__device__ __forceinline__ void cpasync64_f16(const unsigned short* __restrict__ X,
                                              uint32_t sb, uint32_t sa,
                                              int row0, int N, int tid) {
#pragma unroll
    for (int i = tid; i < 1024; i += NT) {
        int r = i >> 4, c8 = i & 15, g = row0 + r;
        cp16(sb + sa + swz(r, c8 * 8), X + (size_t)g * D + c8 * 8, g < N);
    }
}

// --------------------------- fused MLP kernel -------------------------------
#define MS_W    0
#define MS_A    65536
#define MS_B    81920
#define MS_TOT  82944

extern "C" __global__ void __launch_bounds__(NT, 2)
mlp4_kernel(const float* __restrict__ vin, const float* __restrict__ cin,
            const uint4* __restrict__ img,
            const float* __restrict__ b0, const float* __restrict__ b1,
            const float* __restrict__ b2, const float* __restrict__ b3,
            unsigned short* __restrict__ y0, unsigned short* __restrict__ y1,
            unsigned short* __restrict__ y2, unsigned short* __restrict__ y3,
            int V, int C) {
    extern __shared__ char sm[];
    const uint32_t sb = smem_u32(sm);
    const int tid = threadIdx.x, wid = tid >> 5, lane = tid & 31;
    const int wm = wid >> 2, wn = wid & 3;
    float* bs = reinterpret_cast<float*>(sm + MS_B);

    const int tV = (V + 63) >> 6, tC = (C + 63) >> 6;
    const long T = 2L * tV + 2L * tC;
    const int G = gridDim.x;
    int cV = (int)((long)G * tV / T); if (cV < 1) cV = 1;
    int cC = (G - 2 * cV) >> 1; if (cC < 1) cC = 1;
    const int bnd1 = cV, bnd2 = 2 * cV, bnd3 = 2 * cV + cC;

    int seg, start, stride, tiles, N;
    const float* X; const float* bias; unsigned short* Y;
    const int b = blockIdx.x;
    if (b < bnd1)      { seg = 0; start = b;        stride = cV;     }
    else if (b < bnd2) { seg = 1; start = b - bnd1; stride = cV;     }
    else if (b < bnd3) { seg = 2; start = b - bnd2; stride = cC;     }
    else               { seg = 3; start = b - bnd3; stride = G - bnd3; }
    if (seg < 2) { X = vin; N = V; tiles = tV; }
    else         { X = cin; N = C; tiles = tC; }
    bias = (seg == 0) ? b0 : (seg == 1) ? b1 : (seg == 2) ? b2 : b3;
    Y    = (seg == 0) ? y0 : (seg == 1) ? y1 : (seg == 2) ? y2 : y3;
    const uint4* Wimg = img + (size_t)seg * 4096;

#pragma unroll 4
    for (int i = tid; i < 4096; i += NT)
        cp16(sb + MS_W + i * 16, Wimg + i, true);
    if (tid < 2 * D) bs[tid] = bias[tid];
    CP_COMMIT();
    CP_WAIT0();
    __syncthreads();

    for (int t = start; t < tiles; t += stride) {
        const int row0 = t * 64;
        load64_f32(X, sm, MS_A, row0, N, tid);
        __syncthreads();

        float acc[2][4][4];
        zero_acc(acc);
        gemm_pass64(sb + MS_A, sb + MS_W, acc, wm, wn, lane);
        __syncthreads();

#pragma unroll
        for (int s = 0; s < 2; s++) {
#pragma unroll
            for (int nt = 0; nt < 4; nt++) {
                int m = wm * 32 + s * 16 + (lane >> 2);
                int n = wn * 32 + nt * 8 + (lane & 3) * 2;
                float c0 = bs[n], c1 = bs[n + 1];
                uint32_t h0 = pack_h2(fmaxf(acc[s][nt][0] + c0, 0.f),
                                      fmaxf(acc[s][nt][1] + c1, 0.f));
                uint32_t h1 = pack_h2(fmaxf(acc[s][nt][2] + c0, 0.f),
                                      fmaxf(acc[s][nt][3] + c1, 0.f));
                *reinterpret_cast<uint32_t*>(sm + MS_A + swz(m, n)) = h0;
                *reinterpret_cast<uint32_t*>(sm + MS_A + swz(m + 8, n)) = h1;
            }
        }
        __syncthreads();

        zero_acc(acc);
        gemm_pass64(sb + MS_A, sb + MS_W + 32768, acc, wm, wn, lane);

#pragma unroll
        for (int s = 0; s < 2; s++) {
#pragma unroll
            for (int nt = 0; nt < 4; nt++) {
                int m = wm * 32 + s * 16 + (lane >> 2);
                int n = wn * 32 + nt * 8 + (lane & 3) * 2;
                float c0 = bs[D + n], c1 = bs[D + n + 1];
                int g0 = row0 + m, g1 = row0 + m + 8;
                if (g0 < N)
                    *reinterpret_cast<uint32_t*>(Y + (size_t)g0 * D + n) =
                        pack_h2(acc[s][nt][0] + c0, acc[s][nt][1] + c1);
                if (g1 < N)
                    *reinterpret_cast<uint32_t*>(Y + (size_t)g1 * D + n) =
                        pack_h2(acc[s][nt][2] + c0, acc[s][nt][3] + c1);
            }
        }
        __syncthreads();
    }
}

// --------------------------- fused update kernel ----------------------------
// 1 CTA/SM (R10 config). X1/X2 fp16 tiles streamed via cp.async into A1/A2
// while X0 converts into A0; single sync, then 3 back-to-back gemm passes.
#define US_W    0
#define US_A0   98304
#define US_A1   114688
#define US_A2   131072
#define US_B    147456
#define US_TOT  147968

extern "C" __global__ void __launch_bounds__(NT, 1)
update2_kernel(const float* __restrict__ cin, const float* __restrict__ vin,
               const unsigned short* __restrict__ aggc_p,
               const unsigned short* __restrict__ aggc_n,
               const unsigned short* __restrict__ aggv_p,
               const unsigned short* __restrict__ aggv_n,
               const uint4* __restrict__ cuImg, const uint4* __restrict__ vuImg,
               const float* __restrict__ cub, const float* __restrict__ vub,
               float* __restrict__ cout, float* __restrict__ vout,
               int V, int C) {
    extern __shared__ char sm[];
    const uint32_t sb = smem_u32(sm);
    const int tid = threadIdx.x, wid = tid >> 5, lane = tid & 31;
    const int wm = wid >> 2, wn = wid & 3;
    float* bs = reinterpret_cast<float*>(sm + US_B);

    const int tV = (V + 63) >> 6, tC = (C + 63) >> 6;
    const int G = gridDim.x;
    int cC = (int)((long)G * tC / (tC + tV)); if (cC < 1) cC = 1;
    if (cC > G - 1) cC = G - 1;

    int start, stride, tiles, N;
    const float* X0; const unsigned short *X1, *X2;
    const uint4* Wimg; const float* bias; float* Y;
    const int b = blockIdx.x;
    if (b < cC) {
        start = b; stride = cC; tiles = tC; N = C;
        X0 = cin; X1 = aggc_p; X2 = aggc_n;
        Wimg = cuImg; bias = cub; Y = cout;
    } else {
        start = b - cC; stride = G - cC; tiles = tV; N = V;
        X0 = vin; X1 = aggv_p; X2 = aggv_n;
        Wimg = vuImg; bias = vub; Y = vout;
    }

#pragma unroll 4
    for (int i = tid; i < 6144; i += NT)
        cp16(sb + US_W + i * 16, Wimg + i, true);
    if (tid < D) bs[tid] = bias[tid];
    CP_COMMIT();
    CP_WAIT0();
    __syncthreads();

    for (int t = start; t < tiles; t += stride) {
        const int row0 = t * 64;

        // stream fp16 A1/A2 tiles asynchronously
        cpasync64_f16(X1, sb, US_A1, row0, N, tid);
        cpasync64_f16(X2, sb, US_A2, row0, N, tid);
        CP_COMMIT();

        // convert fp32 X0 tile while cp.async flies
        load64_f32(X0, sm, US_A0, row0, N, tid);
        __syncthreads();

        float acc[2][4][4];
        zero_acc(acc);
        gemm_pass64(sb + US_A0, sb + US_W, acc, wm, wn, lane);

        CP_WAIT0();
        __syncthreads();
        gemm_pass64(sb + US_A1, sb + US_W + 32768, acc, wm, wn, lane);
        gemm_pass64(sb + US_A2, sb + US_W + 65536, acc, wm, wn, lane);
        __syncthreads();   // all reads done before next tile overwrites A*

#pragma unroll
        for (int s = 0; s < 2; s++) {
#pragma unroll
            for (int nt = 0; nt < 4; nt++) {
                int m = wm * 32 + s * 16 + (lane >> 2);
                int n = wn * 32 + nt * 8 + (lane & 3) * 2;
                float c0 = bs[n], c1 = bs[n + 1];
                int g0 = row0 + m, g1 = row0 + m + 8;
                if (g0 < N) {
                    float2 o = make_float2(acc[s][nt][0] + c0, acc[s][nt][1] + c1);
                    *reinterpret_cast<float2*>(Y + (size_t)g0 * D + n) = o;
                }
                if (g1 < N) {
                    float2 o = make_float2(acc[s][nt][2] + c0, acc[s][nt][3] + c1);
                    *reinterpret_cast<float2*>(Y + (size_t)g1 * D + n) = o;
                }
            }
        }
    }
}

// ----------------------- fused weight conversion ----------------------------
extern "C" __global__ void wconv_all_kernel(
    const float* __restrict__ W0, const float* __restrict__ W1,
    const float* __restrict__ W2, const float* __restrict__ W3,
    const float* __restrict__ cuW, const float* __restrict__ vuW) {
    int t = blockIdx.x * blockDim.x + threadIdx.x;
    const int MLP_TOT = 4 * 2 * 128 * 128;
    const int UPD_TOT = 384 * 128;
    if (t < MLP_TOT) {
        int w = t >> 15, rest = t & 32767;
        int l = rest >> 14, k = (rest >> 7) & 127, n = rest & 127;
        const float* W = (w == 0) ? W0 : (w == 1) ? W1 : (w == 2) ? W2 : W3;
        __half h = __float2half_rn(W[rest]);
        *reinterpret_cast<__half*>(g_wimg_mlp[w] + (size_t)l * 32768 + swz(n, k)) = h;
    } else if (t < MLP_TOT + UPD_TOT) {
        int u = t - MLP_TOT;
        int k = u >> 7, n = u & 127;
        int s = k >> 7, kl = k & 127;
        __half h = __float2half_rn(cuW[u]);
        *reinterpret_cast<__half*>(g_wimg_cu + (size_t)s * 32768 + swz(n, kl)) = h;
    } else if (t < MLP_TOT + 2 * UPD_TOT) {
        int u = t - MLP_TOT - UPD_TOT;
        int k = u >> 7, n = u & 127;
        int s = k >> 7, kl = k & 127;
        __half h = __float2half_rn(vuW[u]);
        *reinterpret_cast<__half*>(g_wimg_vu + (size_t)s * 32768 + swz(n, kl)) = h;
    }
}

// ----------------------------- fused zero prep ------------------------------
extern "C" __global__ void zero_prep_kernel(int V, int C) {
    int t = blockIdx.x * blockDim.x + threadIdx.x;
    if (t < V) {
        g_degi_pv[t] = 0; g_degi_nv[t] = 0;
        g_fl_pv[t] = 0;   g_fl_nv[t] = 0;
    }
    if (t < C) {
        g_degi_pc[t] = 0; g_degi_nc[t] = 0;
        g_fl_pc[t] = 0;   g_fl_nc[t] = 0;
    }
}

// ------------------------------ CSR build -----------------------------------
extern "C" __global__ void degree_kernel(const int* __restrict__ vE,
                                         const int* __restrict__ cE,
                                         const int* __restrict__ pE,
                                         const int* __restrict__ nE, int Eh) {
    int t = blockIdx.x * blockDim.x + threadIdx.x;
    if (t < Eh) {
        int e = pE[t];
        atomicAdd(&g_degi_pv[vE[e]], 1);
        atomicAdd(&g_degi_pc[cE[e]], 1);
    } else if (t < 2 * Eh) {
        int e = nE[t - Eh];
        atomicAdd(&g_degi_nv[vE[e]], 1);
        atomicAdd(&g_degi_nc[cE[e]], 1);
    }
}

extern "C" __global__ void __launch_bounds__(1024)
scan4_kernel(int V, int C) {
    const int* d; int* r; int n;
    switch (blockIdx.x) {
        case 0:  d = g_degi_pc; r = g_rp_pc; n = C; break;
        case 1:  d = g_degi_nc; r = g_rp_nc; n = C; break;
        case 2:  d = g_degi_pv; r = g_rp_pv; n = V; break;
        default: d = g_degi_nv; r = g_rp_nv; n = V; break;
    }
    __shared__ int wsum[32];
    __shared__ int sh_carry, sh_total;
    int tid = threadIdx.x, lane = tid & 31, wid = tid >> 5;
    if (tid == 0) sh_carry = 0;
    __syncthreads();
    for (int base = 0; base < n; base += 1024) {
        int i = base + tid;
        int v = (i < n) ? d[i] : 0;
        int incl = v;
#pragma unroll
        for (int o = 1; o < 32; o <<= 1) {
            int x = __shfl_up_sync(0xffffffffu, incl, o);
            if (lane >= o) incl += x;
        }
        if (lane == 31) wsum[wid] = incl;
        __syncthreads();
        if (tid < 32) {
            int s = wsum[tid], ip = s;
#pragma unroll
            for (int o = 1; o < 32; o <<= 1) {
                int x = __shfl_up_sync(0xffffffffu, ip, o);
                if (tid >= o) ip += x;
            }
            wsum[tid] = ip - s;
            if (tid == 31) sh_total = ip;
        }
        __syncthreads();
        if (i < n) r[i] = sh_carry + wsum[wid] + incl - v;
        __syncthreads();
        if (tid == 0) sh_carry += sh_total;
        __syncthreads();
    }
    if (tid == 0) r[n] = sh_carry;
}

extern "C" __global__ void fill_kernel(const int* __restrict__ vE,
                                       const int* __restrict__ cE,
                                       const int* __restrict__ pE,
                                       const int* __restrict__ nE, int Eh) {
    int t = blockIdx.x * blockDim.x + threadIdx.x;
    if (t < Eh) {
        int e = pE[t];
        int v = vE[e], c = cE[e];
        float inv = rsqrtf((float)max(g_degi_pv[v], 1) * (float)max(g_degi_pc[c], 1));
        int pos = g_rp_pc[c] + atomicAdd(&g_fl_pc[c], 1);
        g_sl_pc_src[pos] = v;
        g_sl_pc_w[pos] = inv;
        int pos2 = g_rp_pv[v] + atomicAdd(&g_fl_pv[v], 1);
        g_sl_pv_src[pos2] = c;
        g_sl_pv_w[pos2] = inv;
    } else if (t < 2 * Eh) {
        int e = nE[t - Eh];
        int v = vE[e], c = cE[e];
        float inv = rsqrtf((float)max(g_degi_nv[v], 1) * (float)max(g_degi_nc[c], 1));
        int pos = g_rp_nc[c] + atomicAdd(&g_fl_nc[c], 1);
        g_sl_nc_src[pos] = v;
        g_sl_nc_w[pos] = inv;
        int pos2 = g_rp_nv[v] + atomicAdd(&g_fl_nv[v], 1);
        g_sl_nv_src[pos2] = c;
        g_sl_nv_w[pos2] = inv;
    }
}

// ------------------------- fused CSR gather (x4) ----------------------------
extern "C" __global__ void __launch_bounds__(NT)
gather4_kernel(const unsigned short* __restrict__ t_pv2c,
               const unsigned short* __restrict__ t_nv2c,
               const unsigned short* __restrict__ t_pc2v,
               const unsigned short* __restrict__ t_nc2v,
               unsigned short* __restrict__ aggc_p,
               unsigned short* __restrict__ aggc_n,
               unsigned short* __restrict__ aggv_p,
               unsigned short* __restrict__ aggv_n,
               int V, int C) {
    long t = (long)blockIdx.x * blockDim.x + threadIdx.x;
    int gidx = (int)(t >> 4), sub = (int)(t & 15);
    const unsigned short* src; unsigned short* dst;
    const int* rp; const int* sl; const float* wv;
    int node;
    if (gidx < C) {
        node = gidx; src = t_pv2c; dst = aggc_p;
        rp = g_rp_pc; sl = g_sl_pc_src; wv = g_sl_pc_w;
    } else if (gidx < 2 * C) {
        node = gidx - C; src = t_nv2c; dst = aggc_n;
        rp = g_rp_nc; sl = g_sl_nc_src; wv = g_sl_nc_w;
    } else if (gidx < 2 * C + V) {
        node = gidx - 2 * C; src = t_pc2v; dst = aggv_p;
        rp = g_rp_pv; sl = g_sl_pv_src; wv = g_sl_pv_w;
    } else if (gidx < 2 * C + 2 * V) {
        node = gidx - 2 * C - V; src = t_nc2v; dst = aggv_n;
        rp = g_rp_nv; sl = g_sl_nv_src; wv = g_sl_nv_w;
    } else return;

    int j = rp[node], end = rp[node + 1];
    float acc[8] = {0.f, 0.f, 0.f, 0.f, 0.f, 0.f, 0.f, 0.f};
    int s_next = 0; float w_next = 0.f;
    if (j < end) { s_next = __ldg(sl + j); w_next = __ldg(wv + j); }
    while (j < end) {
        int s = s_next; float w = w_next;
        j++;
        if (j < end) { s_next = __ldg(sl + j); w_next = __ldg(wv + j); }
        uint4 x = __ldg(reinterpret_cast<const uint4*>(src + (size_t)s * D) + sub);
        float2 f0 = unpack_h2(x.x), f1 = unpack_h2(x.y);
        float2 f2 = unpack_h2(x.z), f3 = unpack_h2(x.w);
        acc[0] = fmaf(w, f0.x, acc[0]); acc[1] = fmaf(w, f0.y, acc[1]);
        acc[2] = fmaf(w, f1.x, acc[2]); acc[3] = fmaf(w, f1.y, acc[3]);
        acc[4] = fmaf(w, f2.x, acc[4]); acc[5] = fmaf(w, f2.y, acc[5]);
        acc[6] = fmaf(w, f3.x, acc[6]); acc[7] = fmaf(w, f3.y, acc[7]);
    }
    uint4 o;
    o.x = pack_h2(acc[0], acc[1]);
    o.y = pack_h2(acc[2], acc[3]);
    o.z = pack_h2(acc[4], acc[5]);
    o.w = pack_h2(acc[6], acc[7]);
    reinterpret_cast<uint4*>(dst + (size_t)node * D)[sub] = o;
}

// -------------------------------- launch ------------------------------------
extern "C" void kernel_launch(void* const* d_in, const int* in_sizes, int n_in,
                              void* d_out, int out_size) {
    int base = (n_in >= 20) ? 2 : 0;
    const int*   v_edge = (const int*)d_in[base + 0];
    const int*   c_edge = (const int*)d_in[base + 1];
    const int*   p_edge = (const int*)d_in[base + 2];
    const int*   n_edge = (const int*)d_in[base + 3];
    const float* v0     = (const float*)d_in[base + 4];
    const float* c0     = (const float*)d_in[base + 5];
    const float *Wm[4], *Bm[4];
    for (int i = 0; i < 4; i++) {
        Wm[i] = (const float*)d_in[base + 6 + 2 * i];
        Bm[i] = (const float*)d_in[base + 7 + 2 * i];
    }
    const float* cuW = (const float*)d_in[base + 14];
    const float* cub = (const float*)d_in[base + 15];
    const float* vuW = (const float*)d_in[base + 16];
    const float* vub = (const float*)d_in[base + 17];

    const int Eh = in_sizes[base + 2];
    const int V  = in_sizes[base + 4] / D;
    const int C  = in_sizes[base + 5] / D;

    void* p;
    unsigned short *t_pv2c, *t_nv2c, *t_pc2v, *t_nc2v, *agg_c, *agg_v;
    unsigned char *img_mlp, *img_cu, *img_vu;
    cudaGetSymbolAddress(&p, g_t_pv2c); t_pv2c = (unsigned short*)p;
    cudaGetSymbolAddress(&p, g_t_nv2c); t_nv2c = (unsigned short*)p;
    cudaGetSymbolAddress(&p, g_t_pc2v); t_pc2v = (unsigned short*)p;
    cudaGetSymbolAddress(&p, g_t_nc2v); t_nc2v = (unsigned short*)p;
    cudaGetSymbolAddress(&p, g_agg_c);  agg_c  = (unsigned short*)p;
    cudaGetSymbolAddress(&p, g_agg_v);  agg_v  = (unsigned short*)p;
    cudaGetSymbolAddress(&p, g_wimg_mlp); img_mlp = (unsigned char*)p;
    cudaGetSymbolAddress(&p, g_wimg_cu);  img_cu  = (unsigned char*)p;
    cudaGetSymbolAddress(&p, g_wimg_vu);  img_vu  = (unsigned char*)p;

    unsigned short* agg_c_p = agg_c;
    unsigned short* agg_c_n = agg_c + (size_t)CMAX * D;
    unsigned short* agg_v_p = agg_v;
    unsigned short* agg_v_n = agg_v + (size_t)VMAX * D;

    float* outv = (float*)d_out;
    float* outc = outv + (size_t)4 * V * D;

    int sms = 148;
    cudaDeviceGetAttribute(&sms, cudaDevAttrMultiProcessorCount, 0);

    cudaFuncSetAttribute(mlp4_kernel,
                         cudaFuncAttributeMaxDynamicSharedMemorySize, MS_TOT);
    cudaFuncSetAttribute(update2_kernel,
                         cudaFuncAttributeMaxDynamicSharedMemorySize, US_TOT);

    // ---- prep: zero -> degrees -> scan -> fill; fused wconv ----
    {
        int mx = (V > C) ? V : C;
        zero_prep_kernel<<<(mx + NT - 1) / NT, NT>>>(V, C);
        int blk = (2 * Eh + NT - 1) / NT;
        degree_kernel<<<blk, NT>>>(v_edge, c_edge, p_edge, n_edge, Eh);
        scan4_kernel<<<4, 1024>>>(V, C);
        fill_kernel<<<blk, NT>>>(v_edge, c_edge, p_edge, n_edge, Eh);
        const int wtot = 4 * 2 * 128 * 128 + 2 * 384 * 128;
        wconv_all_kernel<<<(wtot + NT - 1) / NT, NT>>>(
            Wm[0], Wm[1], Wm[2], Wm[3], cuW, vuW);
    }

    cudaMemcpyAsync(outv, v0, (size_t)V * D * sizeof(float), cudaMemcpyDeviceToDevice);
    cudaMemcpyAsync(outc, c0, (size_t)C * D * sizeof(float), cudaMemcpyDeviceToDevice);

    const long ggroups = 2L * C + 2L * V;
    const int gblocks = (int)((ggroups * 16 + NT - 1) / NT);

    for (int t = 0; t < 3; t++) {
        const float* vin = outv + (size_t)t * V * D;
        const float* cin = outc + (size_t)t * C * D;
        float* vout = outv + (size_t)(t + 1) * V * D;
        float* cout = outc + (size_t)(t + 1) * C * D;

        mlp4_kernel<<<2 * sms, NT, MS_TOT>>>(
            vin, cin, (const uint4*)img_mlp,
            Bm[0], Bm[1], Bm[2], Bm[3],
            t_pv2c, t_nv2c, t_pc2v, t_nc2v, V, C);

        gather4_kernel<<<gblocks, NT>>>(
            t_pv2c, t_nv2c, t_pc2v, t_nc2v,
            agg_c_p, agg_c_n, agg_v_p, agg_v_n, V, C);

        update2_kernel<<<sms, NT, US_TOT>>>(
            cin, vin, agg_c_p, agg_c_n, agg_v_p, agg_v_n,
            (const uint4*)img_cu, (const uint4*)img_vu,
            cub, vub, cout, vout, V, C);
    }
}

// round 13
// speedup vs baseline: 1.4918x; 1.0618x over previous
#include <cuda_runtime.h>
#include <cuda_fp16.h>
#include <cstdint>

// ---------------------------------------------------------------------------
// GCN_VCG, round 13: fp16 embedding mirrors (ping-pong) + cp.async everywhere.
//  - update2 epilogue stores fp32 to d_out AND fp16 to mirror (bit-identical
//    to the rounding both consumers already performed).
//  - mlp4: A tile cp.async'd fp16, double-buffered (2 CTAs/SM kept).
//  - update2: all 3 A tiles cp.async'd, double-buffered across tiles.
// ---------------------------------------------------------------------------

#define D        128
#define NT       256
#define VMAX     50000
#define CMAX     210000
#define EHMAX    315000

// ------------------------- scratch (no runtime alloc) ----------------------
__device__ unsigned short g_t_pv2c[(size_t)VMAX * D];
__device__ unsigned short g_t_nv2c[(size_t)VMAX * D];
__device__ unsigned short g_t_pc2v[(size_t)CMAX * D];
__device__ unsigned short g_t_nc2v[(size_t)CMAX * D];
__device__ unsigned short g_agg_c[2][(size_t)CMAX * D];
__device__ unsigned short g_agg_v[2][(size_t)VMAX * D];
__device__ unsigned short g_embh_v[2][(size_t)VMAX * D];   // fp16 mirrors
__device__ unsigned short g_embh_c[2][(size_t)CMAX * D];
__device__ unsigned char g_wimg_mlp[4][2 * 32768];
__device__ unsigned char g_wimg_cu[3 * 32768];
__device__ unsigned char g_wimg_vu[3 * 32768];
__device__ int   g_degi_pv[VMAX], g_degi_nv[VMAX];
__device__ int   g_degi_pc[CMAX], g_degi_nc[CMAX];
__device__ int   g_rp_pc[CMAX + 1], g_rp_nc[CMAX + 1];
__device__ int   g_rp_pv[VMAX + 1], g_rp_nv[VMAX + 1];
__device__ int   g_fl_pc[CMAX], g_fl_nc[CMAX], g_fl_pv[VMAX], g_fl_nv[VMAX];
__device__ int   g_sl_pc_src[EHMAX], g_sl_nc_src[EHMAX];
__device__ int   g_sl_pv_src[EHMAX], g_sl_nv_src[EHMAX];
__device__ float g_sl_pc_w[EHMAX], g_sl_nc_w[EHMAX];
__device__ float g_sl_pv_w[EHMAX], g_sl_nv_w[EHMAX];

// ------------------------------ helpers ------------------------------------
__device__ __forceinline__ uint32_t smem_u32(const void* p) {
    uint32_t a;
    asm("{ .reg .u64 t; cvta.to.shared.u64 t, %1; cvt.u32.u64 %0, t; }"
        : "=r"(a) : "l"(p));
    return a;
}

__device__ __host__ __forceinline__ uint32_t swz(int r, int c) {
    return ((uint32_t)r << 8) + ((uint32_t)(((c >> 3) ^ (r & 7)) & 15) << 4)
         + ((uint32_t)(c & 7) << 1);
}

__device__ __forceinline__ uint32_t pack_h2(float a, float b) {
    __half2 h = __floats2half2_rn(a, b);
    return *reinterpret_cast<uint32_t*>(&h);
}

__device__ __forceinline__ float2 unpack_h2(uint32_t u) {
    return __half22float2(*reinterpret_cast<__half2*>(&u));
}

__device__ __forceinline__ void ldm4(uint32_t addr, uint32_t& d0, uint32_t& d1,
                                     uint32_t& d2, uint32_t& d3) {
    asm volatile("ldmatrix.sync.aligned.m8n8.x4.shared.b16 {%0,%1,%2,%3}, [%4];"
                 : "=r"(d0), "=r"(d1), "=r"(d2), "=r"(d3) : "r"(addr));
}

__device__ __forceinline__ void mma16816(float* c, const uint32_t* a,
                                         const uint32_t* b) {
    asm volatile(
        "mma.sync.aligned.m16n8k16.row.col.f32.f16.f16.f32 "
        "{%0,%1,%2,%3}, {%4,%5,%6,%7}, {%8,%9}, {%0,%1,%2,%3};"
        : "+f"(c[0]), "+f"(c[1]), "+f"(c[2]), "+f"(c[3])
        : "r"(a[0]), "r"(a[1]), "r"(a[2]), "r"(a[3]), "r"(b[0]), "r"(b[1]));
}

__device__ __forceinline__ void cp16(uint32_t saddr, const void* g, bool pred) {
    int sz = pred ? 16 : 0;
    asm volatile("cp.async.cg.shared.global [%0], [%1], 16, %2;"
                 :: "r"(saddr), "l"(g), "r"(sz));
}
#define CP_COMMIT() asm volatile("cp.async.commit_group;" ::: "memory")
#define CP_WAIT0()  asm volatile("cp.async.wait_group 0;" ::: "memory")

__device__ __forceinline__ void gemm_pass64(uint32_t sA, uint32_t sW,
                                            float acc[2][4][4],
                                            int wm, int wn, int lane) {
#pragma unroll
    for (int ks = 0; ks < 8; ks++) {
        const int kc = ks * 2;
        uint32_t a[2][4];
#pragma unroll
        for (int s = 0; s < 2; s++) {
            int row = wm * 32 + s * 16 + (lane & 7) + ((lane >> 3) & 1) * 8;
            int chunk = ((kc + (lane >> 4)) ^ (row & 7)) & 15;
            ldm4(sA + row * 256 + chunk * 16, a[s][0], a[s][1], a[s][2], a[s][3]);
        }
        uint32_t b[4][2];
#pragma unroll
        for (int p = 0; p < 2; p++) {
            int row = wn * 32 + p * 16 + (lane & 7) + (lane >> 4) * 8;
            int chunk = ((kc + ((lane >> 3) & 1)) ^ (row & 7)) & 15;
            ldm4(sW + row * 256 + chunk * 16,
                 b[2 * p][0], b[2 * p][1], b[2 * p + 1][0], b[2 * p + 1][1]);
        }
#pragma unroll
        for (int s = 0; s < 2; s++)
#pragma unroll
            for (int nt = 0; nt < 4; nt++)
                mma16816(acc[s][nt], a[s], b[nt]);
    }
}

__device__ __forceinline__ void zero_acc(float acc[2][4][4]) {
#pragma unroll
    for (int s = 0; s < 2; s++)
#pragma unroll
        for (int nt = 0; nt < 4; nt++)
#pragma unroll
            for (int j = 0; j < 4; j++) acc[s][nt][j] = 0.f;
}

// cp.async a 64-row fp16 tile into a swizzled A buffer (16B chunk granularity)
__device__ __forceinline__ void cpasync64_f16(const unsigned short* __restrict__ X,
                                              uint32_t sb, uint32_t sa,
                                              int row0, int N, int tid) {
#pragma unroll
    for (int i = tid; i < 1024; i += NT) {
        int r = i >> 4, c8 = i & 15, g = row0 + r;
        cp16(sb + sa + swz(r, c8 * 8), X + (size_t)g * D + c8 * 8, g < N);
    }
}

// --------------------------- fused MLP kernel -------------------------------
// smem: [W0 32K][W1 32K][A0 16K][A1 16K][bias 1K] = 99328 -> 2 CTAs/SM
#define MS_W    0
#define MS_A    65536
#define MS_B    98304
#define MS_TOT  99328

extern "C" __global__ void __launch_bounds__(NT, 2)
mlp4_kernel(const unsigned short* __restrict__ vinh,
            const unsigned short* __restrict__ cinh,
            const uint4* __restrict__ img,
            const float* __restrict__ b0, const float* __restrict__ b1,
            const float* __restrict__ b2, const float* __restrict__ b3,
            unsigned short* __restrict__ y0, unsigned short* __restrict__ y1,
            unsigned short* __restrict__ y2, unsigned short* __restrict__ y3,
            int V, int C) {
    extern __shared__ char sm[];
    const uint32_t sb = smem_u32(sm);
    const int tid = threadIdx.x, wid = tid >> 5, lane = tid & 31;
    const int wm = wid >> 2, wn = wid & 3;
    float* bs = reinterpret_cast<float*>(sm + MS_B);

    const int tV = (V + 63) >> 6, tC = (C + 63) >> 6;
    const long T = 2L * tV + 2L * tC;
    const int G = gridDim.x;
    int cV = (int)((long)G * tV / T); if (cV < 1) cV = 1;
    int cC = (G - 2 * cV) >> 1; if (cC < 1) cC = 1;
    const int bnd1 = cV, bnd2 = 2 * cV, bnd3 = 2 * cV + cC;

    int seg, start, stride, tiles, N;
    const unsigned short* X; const float* bias; unsigned short* Y;
    const int b = blockIdx.x;
    if (b < bnd1)      { seg = 0; start = b;        stride = cV;     }
    else if (b < bnd2) { seg = 1; start = b - bnd1; stride = cV;     }
    else if (b < bnd3) { seg = 2; start = b - bnd2; stride = cC;     }
    else               { seg = 3; start = b - bnd3; stride = G - bnd3; }
    if (seg < 2) { X = vinh; N = V; tiles = tV; }
    else         { X = cinh; N = C; tiles = tC; }
    bias = (seg == 0) ? b0 : (seg == 1) ? b1 : (seg == 2) ? b2 : b3;
    Y    = (seg == 0) ? y0 : (seg == 1) ? y1 : (seg == 2) ? y2 : y3;
    const uint4* Wimg = img + (size_t)seg * 4096;

#pragma unroll 4
    for (int i = tid; i < 4096; i += NT)
        cp16(sb + MS_W + i * 16, Wimg + i, true);
    if (tid < 2 * D) bs[tid] = bias[tid];
    // prefetch first A tile into buffer 0
    if (start < tiles) cpasync64_f16(X, sb, MS_A, start * 64, N, tid);
    CP_COMMIT();

    int li = 0;
    for (int t = start; t < tiles; t += stride, li++) {
        const int row0 = t * 64;
        const uint32_t Acur = MS_A + (li & 1) * 16384;
        const uint32_t Anxt = MS_A + ((li + 1) & 1) * 16384;

        CP_WAIT0();
        __syncthreads();

        float acc[2][4][4];
        zero_acc(acc);
        gemm_pass64(sb + Acur, sb + MS_W, acc, wm, wn, lane);
        __syncthreads();                 // done reading Acur

        int tn = t + stride;
        if (tn < tiles) cpasync64_f16(X, sb, Anxt, tn * 64, N, tid);
        CP_COMMIT();

        // epilogue 1: bias + relu -> fp16 hidden into Acur
#pragma unroll
        for (int s = 0; s < 2; s++) {
#pragma unroll
            for (int nt = 0; nt < 4; nt++) {
                int m = wm * 32 + s * 16 + (lane >> 2);
                int n = wn * 32 + nt * 8 + (lane & 3) * 2;
                float c0 = bs[n], c1 = bs[n + 1];
                uint32_t h0 = pack_h2(fmaxf(acc[s][nt][0] + c0, 0.f),
                                      fmaxf(acc[s][nt][1] + c1, 0.f));
                uint32_t h1 = pack_h2(fmaxf(acc[s][nt][2] + c0, 0.f),
                                      fmaxf(acc[s][nt][3] + c1, 0.f));
                *reinterpret_cast<uint32_t*>(sm + Acur + swz(m, n)) = h0;
                *reinterpret_cast<uint32_t*>(sm + Acur + swz(m + 8, n)) = h1;
            }
        }
        __syncthreads();

        zero_acc(acc);
        gemm_pass64(sb + Acur, sb + MS_W + 32768, acc, wm, wn, lane);

        // epilogue 2: bias + fp16 store
#pragma unroll
        for (int s = 0; s < 2; s++) {
#pragma unroll
            for (int nt = 0; nt < 4; nt++) {
                int m = wm * 32 + s * 16 + (lane >> 2);
                int n = wn * 32 + nt * 8 + (lane & 3) * 2;
                float c0 = bs[D + n], c1 = bs[D + n + 1];
                int g0 = row0 + m, g1 = row0 + m + 8;
                if (g0 < N)
                    *reinterpret_cast<uint32_t*>(Y + (size_t)g0 * D + n) =
                        pack_h2(acc[s][nt][0] + c0, acc[s][nt][1] + c1);
                if (g1 < N)
                    *reinterpret_cast<uint32_t*>(Y + (size_t)g1 * D + n) =
                        pack_h2(acc[s][nt][2] + c0, acc[s][nt][3] + c1);
            }
        }
        __syncthreads();                 // Acur free before reuse at li+2
    }
}

// --------------------------- fused update kernel ----------------------------
// smem: [W x3 96K][A 2 bufs x 3 x 16K = 96K][bias 512] = 197120, 1 CTA/SM
#define US_W    0
#define US_A    98304
#define US_B    196608
#define US_TOT  197120

extern "C" __global__ void __launch_bounds__(NT, 1)
update2_kernel(const unsigned short* __restrict__ cinh,
               const unsigned short* __restrict__ vinh,
               const unsigned short* __restrict__ aggc_p,
               const unsigned short* __restrict__ aggc_n,
               const unsigned short* __restrict__ aggv_p,
               const unsigned short* __restrict__ aggv_n,
               const uint4* __restrict__ cuImg, const uint4* __restrict__ vuImg,
               const float* __restrict__ cub, const float* __restrict__ vub,
               float* __restrict__ cout, float* __restrict__ vout,
               unsigned short* __restrict__ couth,
               unsigned short* __restrict__ vouth,
               int V, int C) {
    extern __shared__ char sm[];
    const uint32_t sb = smem_u32(sm);
    const int tid = threadIdx.x, wid = tid >> 5, lane = tid & 31;
    const int wm = wid >> 2, wn = wid & 3;
    float* bs = reinterpret_cast<float*>(sm + US_B);

    const int tV = (V + 63) >> 6, tC = (C + 63) >> 6;
    const int G = gridDim.x;
    int cC = (int)((long)G * tC / (tC + tV)); if (cC < 1) cC = 1;
    if (cC > G - 1) cC = G - 1;

    int start, stride, tiles, N;
    const unsigned short *X0, *X1, *X2;
    const uint4* Wimg; const float* bias; float* Y; unsigned short* Yh;
    const int b = blockIdx.x;
    if (b < cC) {
        start = b; stride = cC; tiles = tC; N = C;
        X0 = cinh; X1 = aggc_p; X2 = aggc_n;
        Wimg = cuImg; bias = cub; Y = cout; Yh = couth;
    } else {
        start = b - cC; stride = G - cC; tiles = tV; N = V;
        X0 = vinh; X1 = aggv_p; X2 = aggv_n;
        Wimg = vuImg; bias = vub; Y = vout; Yh = vouth;
    }

#pragma unroll 4
    for (int i = tid; i < 6144; i += NT)
        cp16(sb + US_W + i * 16, Wimg + i, true);
    if (tid < D) bs[tid] = bias[tid];
    // prefetch first tile's 3 A tiles into buffer 0
    if (start < tiles) {
        cpasync64_f16(X0, sb, US_A,         start * 64, N, tid);
        cpasync64_f16(X1, sb, US_A + 16384, start * 64, N, tid);
        cpasync64_f16(X2, sb, US_A + 32768, start * 64, N, tid);
    }
    CP_COMMIT();

    int li = 0;
    for (int t = start; t < tiles; t += stride, li++) {
        const int row0 = t * 64;
        const uint32_t Acur = US_A + (li & 1) * 49152;
        const uint32_t Anxt = US_A + ((li + 1) & 1) * 49152;

        CP_WAIT0();
        __syncthreads();

        int tn = t + stride;
        if (tn < tiles) {
            cpasync64_f16(X0, sb, Anxt,         tn * 64, N, tid);
            cpasync64_f16(X1, sb, Anxt + 16384, tn * 64, N, tid);
            cpasync64_f16(X2, sb, Anxt + 32768, tn * 64, N, tid);
        }
        CP_COMMIT();

        float acc[2][4][4];
        zero_acc(acc);
        gemm_pass64(sb + Acur,         sb + US_W,         acc, wm, wn, lane);
        gemm_pass64(sb + Acur + 16384, sb + US_W + 32768, acc, wm, wn, lane);
        gemm_pass64(sb + Acur + 32768, sb + US_W + 65536, acc, wm, wn, lane);

#pragma unroll
        for (int s = 0; s < 2; s++) {
#pragma unroll
            for (int nt = 0; nt < 4; nt++) {
                int m = wm * 32 + s * 16 + (lane >> 2);
                int n = wn * 32 + nt * 8 + (lane & 3) * 2;
                float c0 = bs[n], c1 = bs[n + 1];
                int g0 = row0 + m, g1 = row0 + m + 8;
                if (g0 < N) {
                    float2 o = make_float2(acc[s][nt][0] + c0, acc[s][nt][1] + c1);
                    *reinterpret_cast<float2*>(Y + (size_t)g0 * D + n) = o;
                    *reinterpret_cast<uint32_t*>(Yh + (size_t)g0 * D + n) =
                        pack_h2(o.x, o.y);
                }
                if (g1 < N) {
                    float2 o = make_float2(acc[s][nt][2] + c0, acc[s][nt][3] + c1);
                    *reinterpret_cast<float2*>(Y + (size_t)g1 * D + n) = o;
                    *reinterpret_cast<uint32_t*>(Yh + (size_t)g1 * D + n) =
                        pack_h2(o.x, o.y);
                }
            }
        }
        __syncthreads();   // all ldmatrix reads of Acur done before reuse
    }
}

// ----------------------- fused weight conversion ----------------------------
extern "C" __global__ void wconv_all_kernel(
    const float* __restrict__ W0, const float* __restrict__ W1,
    const float* __restrict__ W2, const float* __restrict__ W3,
    const float* __restrict__ cuW, const float* __restrict__ vuW) {
    int t = blockIdx.x * blockDim.x + threadIdx.x;
    const int MLP_TOT = 4 * 2 * 128 * 128;
    const int UPD_TOT = 384 * 128;
    if (t < MLP_TOT) {
        int w = t >> 15, rest = t & 32767;
        int l = rest >> 14, k = (rest >> 7) & 127, n = rest & 127;
        const float* W = (w == 0) ? W0 : (w == 1) ? W1 : (w == 2) ? W2 : W3;
        __half h = __float2half_rn(W[rest]);
        *reinterpret_cast<__half*>(g_wimg_mlp[w] + (size_t)l * 32768 + swz(n, k)) = h;
    } else if (t < MLP_TOT + UPD_TOT) {
        int u = t - MLP_TOT;
        int k = u >> 7, n = u & 127;
        int s = k >> 7, kl = k & 127;
        __half h = __float2half_rn(cuW[u]);
        *reinterpret_cast<__half*>(g_wimg_cu + (size_t)s * 32768 + swz(n, kl)) = h;
    } else if (t < MLP_TOT + 2 * UPD_TOT) {
        int u = t - MLP_TOT - UPD_TOT;
        int k = u >> 7, n = u & 127;
        int s = k >> 7, kl = k & 127;
        __half h = __float2half_rn(vuW[u]);
        *reinterpret_cast<__half*>(g_wimg_vu + (size_t)s * 32768 + swz(n, kl)) = h;
    }
}

// -------------------- fp32 -> fp16 embedding mirror (iter 0) ----------------
extern "C" __global__ void emb2h_kernel(const float* __restrict__ v0,
                                        const float* __restrict__ c0,
                                        int V, int C) {
    int t = blockIdx.x * blockDim.x + threadIdx.x;
    int nv = V * (D / 4), nc = C * (D / 4);
    if (t < nv) {
        float4 x = *reinterpret_cast<const float4*>(v0 + (size_t)t * 4);
        *reinterpret_cast<uint2*>(&g_embh_v[0][(size_t)t * 4]) =
            make_uint2(pack_h2(x.x, x.y), pack_h2(x.z, x.w));
    } else if (t < nv + nc) {
        int u = t - nv;
        float4 x = *reinterpret_cast<const float4*>(c0 + (size_t)u * 4);
        *reinterpret_cast<uint2*>(&g_embh_c[0][(size_t)u * 4]) =
            make_uint2(pack_h2(x.x, x.y), pack_h2(x.z, x.w));
    }
}

// ----------------------------- fused zero prep ------------------------------
extern "C" __global__ void zero_prep_kernel(int V, int C) {
    int t = blockIdx.x * blockDim.x + threadIdx.x;
    if (t < V) {
        g_degi_pv[t] = 0; g_degi_nv[t] = 0;
        g_fl_pv[t] = 0;   g_fl_nv[t] = 0;
    }
    if (t < C) {
        g_degi_pc[t] = 0; g_degi_nc[t] = 0;
        g_fl_pc[t] = 0;   g_fl_nc[t] = 0;
    }
}

// ------------------------------ CSR build -----------------------------------
extern "C" __global__ void degree_kernel(const int* __restrict__ vE,
                                         const int* __restrict__ cE,
                                         const int* __restrict__ pE,
                                         const int* __restrict__ nE, int Eh) {
    int t = blockIdx.x * blockDim.x + threadIdx.x;
    if (t < Eh) {
        int e = pE[t];
        atomicAdd(&g_degi_pv[vE[e]], 1);
        atomicAdd(&g_degi_pc[cE[e]], 1);
    } else if (t < 2 * Eh) {
        int e = nE[t - Eh];
        atomicAdd(&g_degi_nv[vE[e]], 1);
        atomicAdd(&g_degi_nc[cE[e]], 1);
    }
}

extern "C" __global__ void __launch_bounds__(1024)
scan4_kernel(int V, int C) {
    const int* d; int* r; int n;
    switch (blockIdx.x) {
        case 0:  d = g_degi_pc; r = g_rp_pc; n = C; break;
        case 1:  d = g_degi_nc; r = g_rp_nc; n = C; break;
        case 2:  d = g_degi_pv; r = g_rp_pv; n = V; break;
        default: d = g_degi_nv; r = g_rp_nv; n = V; break;
    }
    __shared__ int wsum[32];
    __shared__ int sh_carry, sh_total;
    int tid = threadIdx.x, lane = tid & 31, wid = tid >> 5;
    if (tid == 0) sh_carry = 0;
    __syncthreads();
    for (int base = 0; base < n; base += 1024) {
        int i = base + tid;
        int v = (i < n) ? d[i] : 0;
        int incl = v;
#pragma unroll
        for (int o = 1; o < 32; o <<= 1) {
            int x = __shfl_up_sync(0xffffffffu, incl, o);
            if (lane >= o) incl += x;
        }
        if (lane == 31) wsum[wid] = incl;
        __syncthreads();
        if (tid < 32) {
            int s = wsum[tid], ip = s;
#pragma unroll
            for (int o = 1; o < 32; o <<= 1) {
                int x = __shfl_up_sync(0xffffffffu, ip, o);
                if (tid >= o) ip += x;
            }
            wsum[tid] = ip - s;
            if (tid == 31) sh_total = ip;
        }
        __syncthreads();
        if (i < n) r[i] = sh_carry + wsum[wid] + incl - v;
        __syncthreads();
        if (tid == 0) sh_carry += sh_total;
        __syncthreads();
    }
    if (tid == 0) r[n] = sh_carry;
}

extern "C" __global__ void fill_kernel(const int* __restrict__ vE,
                                       const int* __restrict__ cE,
                                       const int* __restrict__ pE,
                                       const int* __restrict__ nE, int Eh) {
    int t = blockIdx.x * blockDim.x + threadIdx.x;
    if (t < Eh) {
        int e = pE[t];
        int v = vE[e], c = cE[e];
        float inv = rsqrtf((float)max(g_degi_pv[v], 1) * (float)max(g_degi_pc[c], 1));
        int pos = g_rp_pc[c] + atomicAdd(&g_fl_pc[c], 1);
        g_sl_pc_src[pos] = v;
        g_sl_pc_w[pos] = inv;
        int pos2 = g_rp_pv[v] + atomicAdd(&g_fl_pv[v], 1);
        g_sl_pv_src[pos2] = c;
        g_sl_pv_w[pos2] = inv;
    } else if (t < 2 * Eh) {
        int e = nE[t - Eh];
        int v = vE[e], c = cE[e];
        float inv = rsqrtf((float)max(g_degi_nv[v], 1) * (float)max(g_degi_nc[c], 1));
        int pos = g_rp_nc[c] + atomicAdd(&g_fl_nc[c], 1);
        g_sl_nc_src[pos] = v;
        g_sl_nc_w[pos] = inv;
        int pos2 = g_rp_nv[v] + atomicAdd(&g_fl_nv[v], 1);
        g_sl_nv_src[pos2] = c;
        g_sl_nv_w[pos2] = inv;
    }
}

// ------------------------- fused CSR gather (x4) ----------------------------
extern "C" __global__ void __launch_bounds__(NT)
gather4_kernel(const unsigned short* __restrict__ t_pv2c,
               const unsigned short* __restrict__ t_nv2c,
               const unsigned short* __restrict__ t_pc2v,
               const unsigned short* __restrict__ t_nc2v,
               unsigned short* __restrict__ aggc_p,
               unsigned short* __restrict__ aggc_n,
               unsigned short* __restrict__ aggv_p,
               unsigned short* __restrict__ aggv_n,
               int V, int C) {
    long t = (long)blockIdx.x * blockDim.x + threadIdx.x;
    int gidx = (int)(t >> 4), sub = (int)(t & 15);
    const unsigned short* src; unsigned short* dst;
    const int* rp; const int* sl; const float* wv;
    int node;
    if (gidx < C) {
        node = gidx; src = t_pv2c; dst = aggc_p;
        rp = g_rp_pc; sl = g_sl_pc_src; wv = g_sl_pc_w;
    } else if (gidx < 2 * C) {
        node = gidx - C; src = t_nv2c; dst = aggc_n;
        rp = g_rp_nc; sl = g_sl_nc_src; wv = g_sl_nc_w;
    } else if (gidx < 2 * C + V) {
        node = gidx - 2 * C; src = t_pc2v; dst = aggv_p;
        rp = g_rp_pv; sl = g_sl_pv_src; wv = g_sl_pv_w;
    } else if (gidx < 2 * C + 2 * V) {
        node = gidx - 2 * C - V; src = t_nc2v; dst = aggv_n;
        rp = g_rp_nv; sl = g_sl_nv_src; wv = g_sl_nv_w;
    } else return;

    int j = rp[node], end = rp[node + 1];
    float acc[8] = {0.f, 0.f, 0.f, 0.f, 0.f, 0.f, 0.f, 0.f};
    int s_next = 0; float w_next = 0.f;
    if (j < end) { s_next = __ldg(sl + j); w_next = __ldg(wv + j); }
    while (j < end) {
        int s = s_next; float w = w_next;
        j++;
        if (j < end) { s_next = __ldg(sl + j); w_next = __ldg(wv + j); }
        uint4 x = __ldg(reinterpret_cast<const uint4*>(src + (size_t)s * D) + sub);
        float2 f0 = unpack_h2(x.x), f1 = unpack_h2(x.y);
        float2 f2 = unpack_h2(x.z), f3 = unpack_h2(x.w);
        acc[0] = fmaf(w, f0.x, acc[0]); acc[1] = fmaf(w, f0.y, acc[1]);
        acc[2] = fmaf(w, f1.x, acc[2]); acc[3] = fmaf(w, f1.y, acc[3]);
        acc[4] = fmaf(w, f2.x, acc[4]); acc[5] = fmaf(w, f2.y, acc[5]);
        acc[6] = fmaf(w, f3.x, acc[6]); acc[7] = fmaf(w, f3.y, acc[7]);
    }
    uint4 o;
    o.x = pack_h2(acc[0], acc[1]);
    o.y = pack_h2(acc[2], acc[3]);
    o.z = pack_h2(acc[4], acc[5]);
    o.w = pack_h2(acc[6], acc[7]);
    reinterpret_cast<uint4*>(dst + (size_t)node * D)[sub] = o;
}

// -------------------------------- launch ------------------------------------
extern "C" void kernel_launch(void* const* d_in, const int* in_sizes, int n_in,
                              void* d_out, int out_size) {
    int base = (n_in >= 20) ? 2 : 0;
    const int*   v_edge = (const int*)d_in[base + 0];
    const int*   c_edge = (const int*)d_in[base + 1];
    const int*   p_edge = (const int*)d_in[base + 2];
    const int*   n_edge = (const int*)d_in[base + 3];
    const float* v0     = (const float*)d_in[base + 4];
    const float* c0     = (const float*)d_in[base + 5];
    const float *Wm[4], *Bm[4];
    for (int i = 0; i < 4; i++) {
        Wm[i] = (const float*)d_in[base + 6 + 2 * i];
        Bm[i] = (const float*)d_in[base + 7 + 2 * i];
    }
    const float* cuW = (const float*)d_in[base + 14];
    const float* cub = (const float*)d_in[base + 15];
    const float* vuW = (const float*)d_in[base + 16];
    const float* vub = (const float*)d_in[base + 17];

    const int Eh = in_sizes[base + 2];
    const int V  = in_sizes[base + 4] / D;
    const int C  = in_sizes[base + 5] / D;

    void* p;
    unsigned short *t_pv2c, *t_nv2c, *t_pc2v, *t_nc2v, *agg_c, *agg_v;
    unsigned short *embh_v, *embh_c;
    unsigned char *img_mlp, *img_cu, *img_vu;
    cudaGetSymbolAddress(&p, g_t_pv2c); t_pv2c = (unsigned short*)p;
    cudaGetSymbolAddress(&p, g_t_nv2c); t_nv2c = (unsigned short*)p;
    cudaGetSymbolAddress(&p, g_t_pc2v); t_pc2v = (unsigned short*)p;
    cudaGetSymbolAddress(&p, g_t_nc2v); t_nc2v = (unsigned short*)p;
    cudaGetSymbolAddress(&p, g_agg_c);  agg_c  = (unsigned short*)p;
    cudaGetSymbolAddress(&p, g_agg_v);  agg_v  = (unsigned short*)p;
    cudaGetSymbolAddress(&p, g_embh_v); embh_v = (unsigned short*)p;
    cudaGetSymbolAddress(&p, g_embh_c); embh_c = (unsigned short*)p;
    cudaGetSymbolAddress(&p, g_wimg_mlp); img_mlp = (unsigned char*)p;
    cudaGetSymbolAddress(&p, g_wimg_cu);  img_cu  = (unsigned char*)p;
    cudaGetSymbolAddress(&p, g_wimg_vu);  img_vu  = (unsigned char*)p;

    unsigned short* agg_c_p = agg_c;
    unsigned short* agg_c_n = agg_c + (size_t)CMAX * D;
    unsigned short* agg_v_p = agg_v;
    unsigned short* agg_v_n = agg_v + (size_t)VMAX * D;

    float* outv = (float*)d_out;
    float* outc = outv + (size_t)4 * V * D;

    int sms = 148;
    cudaDeviceGetAttribute(&sms, cudaDevAttrMultiProcessorCount, 0);

    cudaFuncSetAttribute(mlp4_kernel,
                         cudaFuncAttributeMaxDynamicSharedMemorySize, MS_TOT);
    cudaFuncSetAttribute(update2_kernel,
                         cudaFuncAttributeMaxDynamicSharedMemorySize, US_TOT);

    // ---- prep ----
    {
        int mx = (V > C) ? V : C;
        zero_prep_kernel<<<(mx + NT - 1) / NT, NT>>>(V, C);
        int blk = (2 * Eh + NT - 1) / NT;
        degree_kernel<<<blk, NT>>>(v_edge, c_edge, p_edge, n_edge, Eh);
        scan4_kernel<<<4, 1024>>>(V, C);
        fill_kernel<<<blk, NT>>>(v_edge, c_edge, p_edge, n_edge, Eh);
        const int wtot = 4 * 2 * 128 * 128 + 2 * 384 * 128;
        wconv_all_kernel<<<(wtot + NT - 1) / NT, NT>>>(
            Wm[0], Wm[1], Wm[2], Wm[3], cuW, vuW);
        int etot = (V + C) * (D / 4);
        emb2h_kernel<<<(etot + NT - 1) / NT, NT>>>(v0, c0, V, C);
    }

    cudaMemcpyAsync(outv, v0, (size_t)V * D * sizeof(float), cudaMemcpyDeviceToDevice);
    cudaMemcpyAsync(outc, c0, (size_t)C * D * sizeof(float), cudaMemcpyDeviceToDevice);

    const long ggroups = 2L * C + 2L * V;
    const int gblocks = (int)((ggroups * 16 + NT - 1) / NT);

    for (int t = 0; t < 3; t++) {
        const unsigned short* vinh = embh_v + (size_t)(t & 1) * VMAX * D;
        const unsigned short* cinh = embh_c + (size_t)(t & 1) * CMAX * D;
        unsigned short* vouth = embh_v + (size_t)((t + 1) & 1) * VMAX * D;
        unsigned short* couth = embh_c + (size_t)((t + 1) & 1) * CMAX * D;
        float* vout = outv + (size_t)(t + 1) * V * D;
        float* cout = outc + (size_t)(t + 1) * C * D;

        mlp4_kernel<<<2 * sms, NT, MS_TOT>>>(
            vinh, cinh, (const uint4*)img_mlp,
            Bm[0], Bm[1], Bm[2], Bm[3],
            t_pv2c, t_nv2c, t_pc2v, t_nc2v, V, C);

        gather4_kernel<<<gblocks, NT>>>(
            t_pv2c, t_nv2c, t_pc2v, t_nc2v,
            agg_c_p, agg_c_n, agg_v_p, agg_v_n, V, C);

        update2_kernel<<<sms, NT, US_TOT>>>(
            cinh, vinh, agg_c_p, agg_c_n, agg_v_p, agg_v_n,
            (const uint4*)img_cu, (const uint4*)img_vu,
            cub, vub, cout, vout, couth, vouth, V, C);
    }
}

// round 14
// speedup vs baseline: 1.5300x; 1.0256x over previous
#include <cuda_runtime.h>
#include <cuda_fp16.h>
#include <cstdint>

// ---------------------------------------------------------------------------
// GCN_VCG, round 14: two-stream fork-join of the independent v/c chains.
//  chain A (stream 0): mlpV -> gatherC -> updateC   (needs B's vouth of t-1)
//  chain B (stream 2): mlpC -> gatherV -> updateV   (needs A's couth of t-1)
//  Cross-chain deps expressed with 2 ping-ponged events (capture-legal fork).
//  Kernel math identical to R13 (fp16 GEMMs, fp16 mirrors, cp.async A tiles).
// ---------------------------------------------------------------------------

#define D        128
#define NT       256
#define VMAX     50000
#define CMAX     210000
#define EHMAX    315000

// ------------------------- scratch (no runtime alloc) ----------------------
__device__ unsigned short g_t_pv2c[(size_t)VMAX * D];
__device__ unsigned short g_t_nv2c[(size_t)VMAX * D];
__device__ unsigned short g_t_pc2v[(size_t)CMAX * D];
__device__ unsigned short g_t_nc2v[(size_t)CMAX * D];
__device__ unsigned short g_agg_c[2][(size_t)CMAX * D];
__device__ unsigned short g_agg_v[2][(size_t)VMAX * D];
__device__ unsigned short g_embh_v[2][(size_t)VMAX * D];
__device__ unsigned short g_embh_c[2][(size_t)CMAX * D];
__device__ unsigned char g_wimg_mlp[4][2 * 32768];
__device__ unsigned char g_wimg_cu[3 * 32768];
__device__ unsigned char g_wimg_vu[3 * 32768];
__device__ int   g_degi_pv[VMAX], g_degi_nv[VMAX];
__device__ int   g_degi_pc[CMAX], g_degi_nc[CMAX];
__device__ int   g_rp_pc[CMAX + 1], g_rp_nc[CMAX + 1];
__device__ int   g_rp_pv[VMAX + 1], g_rp_nv[VMAX + 1];
__device__ int   g_fl_pc[CMAX], g_fl_nc[CMAX], g_fl_pv[VMAX], g_fl_nv[VMAX];
__device__ int   g_sl_pc_src[EHMAX], g_sl_nc_src[EHMAX];
__device__ int   g_sl_pv_src[EHMAX], g_sl_nv_src[EHMAX];
__device__ float g_sl_pc_w[EHMAX], g_sl_nc_w[EHMAX];
__device__ float g_sl_pv_w[EHMAX], g_sl_nv_w[EHMAX];

// ------------------------------ helpers ------------------------------------
__device__ __forceinline__ uint32_t smem_u32(const void* p) {
    uint32_t a;
    asm("{ .reg .u64 t; cvta.to.shared.u64 t, %1; cvt.u32.u64 %0, t; }"
        : "=r"(a) : "l"(p));
    return a;
}

__device__ __host__ __forceinline__ uint32_t swz(int r, int c) {
    return ((uint32_t)r << 8) + ((uint32_t)(((c >> 3) ^ (r & 7)) & 15) << 4)
         + ((uint32_t)(c & 7) << 1);
}

__device__ __forceinline__ uint32_t pack_h2(float a, float b) {
    __half2 h = __floats2half2_rn(a, b);
    return *reinterpret_cast<uint32_t*>(&h);
}

__device__ __forceinline__ float2 unpack_h2(uint32_t u) {
    return __half22float2(*reinterpret_cast<__half2*>(&u));
}

__device__ __forceinline__ void ldm4(uint32_t addr, uint32_t& d0, uint32_t& d1,
                                     uint32_t& d2, uint32_t& d3) {
    asm volatile("ldmatrix.sync.aligned.m8n8.x4.shared.b16 {%0,%1,%2,%3}, [%4];"
                 : "=r"(d0), "=r"(d1), "=r"(d2), "=r"(d3) : "r"(addr));
}

__device__ __forceinline__ void mma16816(float* c, const uint32_t* a,
                                         const uint32_t* b) {
    asm volatile(
        "mma.sync.aligned.m16n8k16.row.col.f32.f16.f16.f32 "
        "{%0,%1,%2,%3}, {%4,%5,%6,%7}, {%8,%9}, {%0,%1,%2,%3};"
        : "+f"(c[0]), "+f"(c[1]), "+f"(c[2]), "+f"(c[3])
        : "r"(a[0]), "r"(a[1]), "r"(a[2]), "r"(a[3]), "r"(b[0]), "r"(b[1]));
}

__device__ __forceinline__ void cp16(uint32_t saddr, const void* g, bool pred) {
    int sz = pred ? 16 : 0;
    asm volatile("cp.async.cg.shared.global [%0], [%1], 16, %2;"
                 :: "r"(saddr), "l"(g), "r"(sz));
}
#define CP_COMMIT() asm volatile("cp.async.commit_group;" ::: "memory")
#define CP_WAIT0()  asm volatile("cp.async.wait_group 0;" ::: "memory")

__device__ __forceinline__ void gemm_pass64(uint32_t sA, uint32_t sW,
                                            float acc[2][4][4],
                                            int wm, int wn, int lane) {
#pragma unroll
    for (int ks = 0; ks < 8; ks++) {
        const int kc = ks * 2;
        uint32_t a[2][4];
#pragma unroll
        for (int s = 0; s < 2; s++) {
            int row = wm * 32 + s * 16 + (lane & 7) + ((lane >> 3) & 1) * 8;
            int chunk = ((kc + (lane >> 4)) ^ (row & 7)) & 15;
            ldm4(sA + row * 256 + chunk * 16, a[s][0], a[s][1], a[s][2], a[s][3]);
        }
        uint32_t b[4][2];
#pragma unroll
        for (int p = 0; p < 2; p++) {
            int row = wn * 32 + p * 16 + (lane & 7) + (lane >> 4) * 8;
            int chunk = ((kc + ((lane >> 3) & 1)) ^ (row & 7)) & 15;
            ldm4(sW + row * 256 + chunk * 16,
                 b[2 * p][0], b[2 * p][1], b[2 * p + 1][0], b[2 * p + 1][1]);
        }
#pragma unroll
        for (int s = 0; s < 2; s++)
#pragma unroll
            for (int nt = 0; nt < 4; nt++)
                mma16816(acc[s][nt], a[s], b[nt]);
    }
}

__device__ __forceinline__ void zero_acc(float acc[2][4][4]) {
#pragma unroll
    for (int s = 0; s < 2; s++)
#pragma unroll
        for (int nt = 0; nt < 4; nt++)
#pragma unroll
            for (int j = 0; j < 4; j++) acc[s][nt][j] = 0.f;
}

__device__ __forceinline__ void cpasync64_f16(const unsigned short* __restrict__ X,
                                              uint32_t sb, uint32_t sa,
                                              int row0, int N, int tid) {
#pragma unroll
    for (int i = tid; i < 1024; i += NT) {
        int r = i >> 4, c8 = i & 15, g = row0 + r;
        cp16(sb + sa + swz(r, c8 * 8), X + (size_t)g * D + c8 * 8, g < N);
    }
}

// --------------------------- 2-segment MLP kernel ---------------------------
// smem: [W0 32K][W1 32K][A0 16K][A1 16K][bias 1K] = 99328 -> 2 CTAs/SM
#define MS_W    0
#define MS_A    65536
#define MS_B    98304
#define MS_TOT  99328

extern "C" __global__ void __launch_bounds__(NT, 2)
mlp2seg_kernel(const unsigned short* __restrict__ Xh,
               const uint4* __restrict__ imgA, const uint4* __restrict__ imgB,
               const float* __restrict__ biasA, const float* __restrict__ biasB,
               unsigned short* __restrict__ yA, unsigned short* __restrict__ yB,
               int N) {
    extern __shared__ char sm[];
    const uint32_t sb = smem_u32(sm);
    const int tid = threadIdx.x, wid = tid >> 5, lane = tid & 31;
    const int wm = wid >> 2, wn = wid & 3;
    float* bs = reinterpret_cast<float*>(sm + MS_B);

    const int tiles = (N + 63) >> 6;
    const int G = gridDim.x, half = G >> 1;
    const int seg = (blockIdx.x < half) ? 0 : 1;
    const int start = seg ? blockIdx.x - half : blockIdx.x;
    const int stride = seg ? (G - half) : half;
    const uint4* Wimg = seg ? imgB : imgA;
    const float* bias = seg ? biasB : biasA;
    unsigned short* Y = seg ? yB : yA;

#pragma unroll 4
    for (int i = tid; i < 4096; i += NT)
        cp16(sb + MS_W + i * 16, Wimg + i, true);
    if (tid < 2 * D) bs[tid] = bias[tid];
    if (start < tiles) cpasync64_f16(Xh, sb, MS_A, start * 64, N, tid);
    CP_COMMIT();

    int li = 0;
    for (int t = start; t < tiles; t += stride, li++) {
        const int row0 = t * 64;
        const uint32_t Acur = MS_A + (li & 1) * 16384;
        const uint32_t Anxt = MS_A + ((li + 1) & 1) * 16384;

        CP_WAIT0();
        __syncthreads();

        float acc[2][4][4];
        zero_acc(acc);
        gemm_pass64(sb + Acur, sb + MS_W, acc, wm, wn, lane);
        __syncthreads();

        int tn = t + stride;
        if (tn < tiles) cpasync64_f16(Xh, sb, Anxt, tn * 64, N, tid);
        CP_COMMIT();

#pragma unroll
        for (int s = 0; s < 2; s++) {
#pragma unroll
            for (int nt = 0; nt < 4; nt++) {
                int m = wm * 32 + s * 16 + (lane >> 2);
                int n = wn * 32 + nt * 8 + (lane & 3) * 2;
                float c0 = bs[n], c1 = bs[n + 1];
                uint32_t h0 = pack_h2(fmaxf(acc[s][nt][0] + c0, 0.f),
                                      fmaxf(acc[s][nt][1] + c1, 0.f));
                uint32_t h1 = pack_h2(fmaxf(acc[s][nt][2] + c0, 0.f),
                                      fmaxf(acc[s][nt][3] + c1, 0.f));
                *reinterpret_cast<uint32_t*>(sm + Acur + swz(m, n)) = h0;
                *reinterpret_cast<uint32_t*>(sm + Acur + swz(m + 8, n)) = h1;
            }
        }
        __syncthreads();

        zero_acc(acc);
        gemm_pass64(sb + Acur, sb + MS_W + 32768, acc, wm, wn, lane);

#pragma unroll
        for (int s = 0; s < 2; s++) {
#pragma unroll
            for (int nt = 0; nt < 4; nt++) {
                int m = wm * 32 + s * 16 + (lane >> 2);
                int n = wn * 32 + nt * 8 + (lane & 3) * 2;
                float c0 = bs[D + n], c1 = bs[D + n + 1];
                int g0 = row0 + m, g1 = row0 + m + 8;
                if (g0 < N)
                    *reinterpret_cast<uint32_t*>(Y + (size_t)g0 * D + n) =
                        pack_h2(acc[s][nt][0] + c0, acc[s][nt][1] + c1);
                if (g1 < N)
                    *reinterpret_cast<uint32_t*>(Y + (size_t)g1 * D + n) =
                        pack_h2(acc[s][nt][2] + c0, acc[s][nt][3] + c1);
            }
        }
        __syncthreads();
    }
}

// --------------------------- single update kernel ---------------------------
// smem: [W x3 96K][A 2x48K][bias 512] = 197120, 1 CTA/SM
#define US_W    0
#define US_A    98304
#define US_B    196608
#define US_TOT  197120

extern "C" __global__ void __launch_bounds__(NT, 1)
update1_kernel(const unsigned short* __restrict__ X0,
               const unsigned short* __restrict__ X1,
               const unsigned short* __restrict__ X2,
               const uint4* __restrict__ Wimg, const float* __restrict__ bias,
               float* __restrict__ Y, unsigned short* __restrict__ Yh, int N) {
    extern __shared__ char sm[];
    const uint32_t sb = smem_u32(sm);
    const int tid = threadIdx.x, wid = tid >> 5, lane = tid & 31;
    const int wm = wid >> 2, wn = wid & 3;
    float* bs = reinterpret_cast<float*>(sm + US_B);
    const int tiles = (N + 63) >> 6;
    const int start = blockIdx.x, stride = gridDim.x;

#pragma unroll 4
    for (int i = tid; i < 6144; i += NT)
        cp16(sb + US_W + i * 16, Wimg + i, true);
    if (tid < D) bs[tid] = bias[tid];
    if (start < tiles) {
        cpasync64_f16(X0, sb, US_A,         start * 64, N, tid);
        cpasync64_f16(X1, sb, US_A + 16384, start * 64, N, tid);
        cpasync64_f16(X2, sb, US_A + 32768, start * 64, N, tid);
    }
    CP_COMMIT();

    int li = 0;
    for (int t = start; t < tiles; t += stride, li++) {
        const int row0 = t * 64;
        const uint32_t Acur = US_A + (li & 1) * 49152;
        const uint32_t Anxt = US_A + ((li + 1) & 1) * 49152;

        CP_WAIT0();
        __syncthreads();

        int tn = t + stride;
        if (tn < tiles) {
            cpasync64_f16(X0, sb, Anxt,         tn * 64, N, tid);
            cpasync64_f16(X1, sb, Anxt + 16384, tn * 64, N, tid);
            cpasync64_f16(X2, sb, Anxt + 32768, tn * 64, N, tid);
        }
        CP_COMMIT();

        float acc[2][4][4];
        zero_acc(acc);
        gemm_pass64(sb + Acur,         sb + US_W,         acc, wm, wn, lane);
        gemm_pass64(sb + Acur + 16384, sb + US_W + 32768, acc, wm, wn, lane);
        gemm_pass64(sb + Acur + 32768, sb + US_W + 65536, acc, wm, wn, lane);

#pragma unroll
        for (int s = 0; s < 2; s++) {
#pragma unroll
            for (int nt = 0; nt < 4; nt++) {
                int m = wm * 32 + s * 16 + (lane >> 2);
                int n = wn * 32 + nt * 8 + (lane & 3) * 2;
                float c0 = bs[n], c1 = bs[n + 1];
                int g0 = row0 + m, g1 = row0 + m + 8;
                if (g0 < N) {
                    float2 o = make_float2(acc[s][nt][0] + c0, acc[s][nt][1] + c1);
                    *reinterpret_cast<float2*>(Y + (size_t)g0 * D + n) = o;
                    *reinterpret_cast<uint32_t*>(Yh + (size_t)g0 * D + n) =
                        pack_h2(o.x, o.y);
                }
                if (g1 < N) {
                    float2 o = make_float2(acc[s][nt][2] + c0, acc[s][nt][3] + c1);
                    *reinterpret_cast<float2*>(Y + (size_t)g1 * D + n) = o;
                    *reinterpret_cast<uint32_t*>(Yh + (size_t)g1 * D + n) =
                        pack_h2(o.x, o.y);
                }
            }
        }
        __syncthreads();
    }
}

// ------------------------- 2-set CSR gather ---------------------------------
extern "C" __global__ void __launch_bounds__(NT)
gather2_kernel(const unsigned short* __restrict__ srcA,
               const unsigned short* __restrict__ srcB,
               unsigned short* __restrict__ dstA,
               unsigned short* __restrict__ dstB,
               const int* __restrict__ rpA, const int* __restrict__ slA,
               const float* __restrict__ wvA,
               const int* __restrict__ rpB, const int* __restrict__ slB,
               const float* __restrict__ wvB, int n) {
    long t = (long)blockIdx.x * blockDim.x + threadIdx.x;
    int gidx = (int)(t >> 4), sub = (int)(t & 15);
    if (gidx >= 2 * n) return;
    int node; const unsigned short* src; unsigned short* dst;
    const int *rp, *sl; const float* wv;
    if (gidx < n) { node = gidx;     src = srcA; dst = dstA; rp = rpA; sl = slA; wv = wvA; }
    else          { node = gidx - n; src = srcB; dst = dstB; rp = rpB; sl = slB; wv = wvB; }

    int j = rp[node], end = rp[node + 1];
    float acc[8] = {0.f, 0.f, 0.f, 0.f, 0.f, 0.f, 0.f, 0.f};
    int s_next = 0; float w_next = 0.f;
    if (j < end) { s_next = __ldg(sl + j); w_next = __ldg(wv + j); }
    while (j < end) {
        int s = s_next; float w = w_next;
        j++;
        if (j < end) { s_next = __ldg(sl + j); w_next = __ldg(wv + j); }
        uint4 x = __ldg(reinterpret_cast<const uint4*>(src + (size_t)s * D) + sub);
        float2 f0 = unpack_h2(x.x), f1 = unpack_h2(x.y);
        float2 f2 = unpack_h2(x.z), f3 = unpack_h2(x.w);
        acc[0] = fmaf(w, f0.x, acc[0]); acc[1] = fmaf(w, f0.y, acc[1]);
        acc[2] = fmaf(w, f1.x, acc[2]); acc[3] = fmaf(w, f1.y, acc[3]);
        acc[4] = fmaf(w, f2.x, acc[4]); acc[5] = fmaf(w, f2.y, acc[5]);
        acc[6] = fmaf(w, f3.x, acc[6]); acc[7] = fmaf(w, f3.y, acc[7]);
    }
    uint4 o;
    o.x = pack_h2(acc[0], acc[1]);
    o.y = pack_h2(acc[2], acc[3]);
    o.z = pack_h2(acc[4], acc[5]);
    o.w = pack_h2(acc[6], acc[7]);
    reinterpret_cast<uint4*>(dst + (size_t)node * D)[sub] = o;
}

// ----------------------- fused weight conversion ----------------------------
extern "C" __global__ void wconv_all_kernel(
    const float* __restrict__ W0, const float* __restrict__ W1,
    const float* __restrict__ W2, const float* __restrict__ W3,
    const float* __restrict__ cuW, const float* __restrict__ vuW) {
    int t = blockIdx.x * blockDim.x + threadIdx.x;
    const int MLP_TOT = 4 * 2 * 128 * 128;
    const int UPD_TOT = 384 * 128;
    if (t < MLP_TOT) {
        int w = t >> 15, rest = t & 32767;
        int l = rest >> 14, k = (rest >> 7) & 127, n = rest & 127;
        const float* W = (w == 0) ? W0 : (w == 1) ? W1 : (w == 2) ? W2 : W3;
        __half h = __float2half_rn(W[rest]);
        *reinterpret_cast<__half*>(g_wimg_mlp[w] + (size_t)l * 32768 + swz(n, k)) = h;
    } else if (t < MLP_TOT + UPD_TOT) {
        int u = t - MLP_TOT;
        int k = u >> 7, n = u & 127;
        int s = k >> 7, kl = k & 127;
        __half h = __float2half_rn(cuW[u]);
        *reinterpret_cast<__half*>(g_wimg_cu + (size_t)s * 32768 + swz(n, kl)) = h;
    } else if (t < MLP_TOT + 2 * UPD_TOT) {
        int u = t - MLP_TOT - UPD_TOT;
        int k = u >> 7, n = u & 127;
        int s = k >> 7, kl = k & 127;
        __half h = __float2half_rn(vuW[u]);
        *reinterpret_cast<__half*>(g_wimg_vu + (size_t)s * 32768 + swz(n, kl)) = h;
    }
}

extern "C" __global__ void emb2h_kernel(const float* __restrict__ v0,
                                        const float* __restrict__ c0,
                                        int V, int C) {
    int t = blockIdx.x * blockDim.x + threadIdx.x;
    int nv = V * (D / 4), nc = C * (D / 4);
    if (t < nv) {
        float4 x = *reinterpret_cast<const float4*>(v0 + (size_t)t * 4);
        *reinterpret_cast<uint2*>(&g_embh_v[0][(size_t)t * 4]) =
            make_uint2(pack_h2(x.x, x.y), pack_h2(x.z, x.w));
    } else if (t < nv + nc) {
        int u = t - nv;
        float4 x = *reinterpret_cast<const float4*>(c0 + (size_t)u * 4);
        *reinterpret_cast<uint2*>(&g_embh_c[0][(size_t)u * 4]) =
            make_uint2(pack_h2(x.x, x.y), pack_h2(x.z, x.w));
    }
}

extern "C" __global__ void zero_prep_kernel(int V, int C) {
    int t = blockIdx.x * blockDim.x + threadIdx.x;
    if (t < V) {
        g_degi_pv[t] = 0; g_degi_nv[t] = 0;
        g_fl_pv[t] = 0;   g_fl_nv[t] = 0;
    }
    if (t < C) {
        g_degi_pc[t] = 0; g_degi_nc[t] = 0;
        g_fl_pc[t] = 0;   g_fl_nc[t] = 0;
    }
}

extern "C" __global__ void degree_kernel(const int* __restrict__ vE,
                                         const int* __restrict__ cE,
                                         const int* __restrict__ pE,
                                         const int* __restrict__ nE, int Eh) {
    int t = blockIdx.x * blockDim.x + threadIdx.x;
    if (t < Eh) {
        int e = pE[t];
        atomicAdd(&g_degi_pv[vE[e]], 1);
        atomicAdd(&g_degi_pc[cE[e]], 1);
    } else if (t < 2 * Eh) {
        int e = nE[t - Eh];
        atomicAdd(&g_degi_nv[vE[e]], 1);
        atomicAdd(&g_degi_nc[cE[e]], 1);
    }
}

extern "C" __global__ void __launch_bounds__(1024)
scan4_kernel(int V, int C) {
    const int* d; int* r; int n;
    switch (blockIdx.x) {
        case 0:  d = g_degi_pc; r = g_rp_pc; n = C; break;
        case 1:  d = g_degi_nc; r = g_rp_nc; n = C; break;
        case 2:  d = g_degi_pv; r = g_rp_pv; n = V; break;
        default: d = g_degi_nv; r = g_rp_nv; n = V; break;
    }
    __shared__ int wsum[32];
    __shared__ int sh_carry, sh_total;
    int tid = threadIdx.x, lane = tid & 31, wid = tid >> 5;
    if (tid == 0) sh_carry = 0;
    __syncthreads();
    for (int base = 0; base < n; base += 1024) {
        int i = base + tid;
        int v = (i < n) ? d[i] : 0;
        int incl = v;
#pragma unroll
        for (int o = 1; o < 32; o <<= 1) {
            int x = __shfl_up_sync(0xffffffffu, incl, o);
            if (lane >= o) incl += x;
        }
        if (lane == 31) wsum[wid] = incl;
        __syncthreads();
        if (tid < 32) {
            int s = wsum[tid], ip = s;
#pragma unroll
            for (int o = 1; o < 32; o <<= 1) {
                int x = __shfl_up_sync(0xffffffffu, ip, o);
                if (tid >= o) ip += x;
            }
            wsum[tid] = ip - s;
            if (tid == 31) sh_total = ip;
        }
        __syncthreads();
        if (i < n) r[i] = sh_carry + wsum[wid] + incl - v;
        __syncthreads();
        if (tid == 0) sh_carry += sh_total;
        __syncthreads();
    }
    if (tid == 0) r[n] = sh_carry;
}

extern "C" __global__ void fill_kernel(const int* __restrict__ vE,
                                       const int* __restrict__ cE,
                                       const int* __restrict__ pE,
                                       const int* __restrict__ nE, int Eh) {
    int t = blockIdx.x * blockDim.x + threadIdx.x;
    if (t < Eh) {
        int e = pE[t];
        int v = vE[e], c = cE[e];
        float inv = rsqrtf((float)max(g_degi_pv[v], 1) * (float)max(g_degi_pc[c], 1));
        int pos = g_rp_pc[c] + atomicAdd(&g_fl_pc[c], 1);
        g_sl_pc_src[pos] = v;
        g_sl_pc_w[pos] = inv;
        int pos2 = g_rp_pv[v] + atomicAdd(&g_fl_pv[v], 1);
        g_sl_pv_src[pos2] = c;
        g_sl_pv_w[pos2] = inv;
    } else if (t < 2 * Eh) {
        int e = nE[t - Eh];
        int v = vE[e], c = cE[e];
        float inv = rsqrtf((float)max(g_degi_nv[v], 1) * (float)max(g_degi_nc[c], 1));
        int pos = g_rp_nc[c] + atomicAdd(&g_fl_nc[c], 1);
        g_sl_nc_src[pos] = v;
        g_sl_nc_w[pos] = inv;
        int pos2 = g_rp_nv[v] + atomicAdd(&g_fl_nv[v], 1);
        g_sl_nv_src[pos2] = c;
        g_sl_nv_w[pos2] = inv;
    }
}

// -------------------------------- launch ------------------------------------
extern "C" void kernel_launch(void* const* d_in, const int* in_sizes, int n_in,
                              void* d_out, int out_size) {
    int base = (n_in >= 20) ? 2 : 0;
    const int*   v_edge = (const int*)d_in[base + 0];
    const int*   c_edge = (const int*)d_in[base + 1];
    const int*   p_edge = (const int*)d_in[base + 2];
    const int*   n_edge = (const int*)d_in[base + 3];
    const float* v0     = (const float*)d_in[base + 4];
    const float* c0     = (const float*)d_in[base + 5];
    const float *Wm[4], *Bm[4];
    for (int i = 0; i < 4; i++) {
        Wm[i] = (const float*)d_in[base + 6 + 2 * i];
        Bm[i] = (const float*)d_in[base + 7 + 2 * i];
    }
    const float* cuW = (const float*)d_in[base + 14];
    const float* cub = (const float*)d_in[base + 15];
    const float* vuW = (const float*)d_in[base + 16];
    const float* vub = (const float*)d_in[base + 17];

    const int Eh = in_sizes[base + 2];
    const int V  = in_sizes[base + 4] / D;
    const int C  = in_sizes[base + 5] / D;

    void* p;
    unsigned short *t_pv2c, *t_nv2c, *t_pc2v, *t_nc2v, *agg_c, *agg_v;
    unsigned short *embh_v, *embh_c;
    unsigned char *img_mlp, *img_cu, *img_vu;
    int *rp_pc, *rp_nc, *rp_pv, *rp_nv;
    int *sl_pc_s, *sl_nc_s, *sl_pv_s, *sl_nv_s;
    float *sl_pc_w, *sl_nc_w, *sl_pv_w, *sl_nv_w;
    cudaGetSymbolAddress(&p, g_t_pv2c); t_pv2c = (unsigned short*)p;
    cudaGetSymbolAddress(&p, g_t_nv2c); t_nv2c = (unsigned short*)p;
    cudaGetSymbolAddress(&p, g_t_pc2v); t_pc2v = (unsigned short*)p;
    cudaGetSymbolAddress(&p, g_t_nc2v); t_nc2v = (unsigned short*)p;
    cudaGetSymbolAddress(&p, g_agg_c);  agg_c  = (unsigned short*)p;
    cudaGetSymbolAddress(&p, g_agg_v);  agg_v  = (unsigned short*)p;
    cudaGetSymbolAddress(&p, g_embh_v); embh_v = (unsigned short*)p;
    cudaGetSymbolAddress(&p, g_embh_c); embh_c = (unsigned short*)p;
    cudaGetSymbolAddress(&p, g_wimg_mlp); img_mlp = (unsigned char*)p;
    cudaGetSymbolAddress(&p, g_wimg_cu);  img_cu  = (unsigned char*)p;
    cudaGetSymbolAddress(&p, g_wimg_vu);  img_vu  = (unsigned char*)p;
    cudaGetSymbolAddress(&p, g_rp_pc); rp_pc = (int*)p;
    cudaGetSymbolAddress(&p, g_rp_nc); rp_nc = (int*)p;
    cudaGetSymbolAddress(&p, g_rp_pv); rp_pv = (int*)p;
    cudaGetSymbolAddress(&p, g_rp_nv); rp_nv = (int*)p;
    cudaGetSymbolAddress(&p, g_sl_pc_src); sl_pc_s = (int*)p;
    cudaGetSymbolAddress(&p, g_sl_nc_src); sl_nc_s = (int*)p;
    cudaGetSymbolAddress(&p, g_sl_pv_src); sl_pv_s = (int*)p;
    cudaGetSymbolAddress(&p, g_sl_nv_src); sl_nv_s = (int*)p;
    cudaGetSymbolAddress(&p, g_sl_pc_w); sl_pc_w = (float*)p;
    cudaGetSymbolAddress(&p, g_sl_nc_w); sl_nc_w = (float*)p;
    cudaGetSymbolAddress(&p, g_sl_pv_w); sl_pv_w = (float*)p;
    cudaGetSymbolAddress(&p, g_sl_nv_w); sl_nv_w = (float*)p;

    unsigned short* agg_c_p = agg_c;
    unsigned short* agg_c_n = agg_c + (size_t)CMAX * D;
    unsigned short* agg_v_p = agg_v;
    unsigned short* agg_v_n = agg_v + (size_t)VMAX * D;

    float* outv = (float*)d_out;
    float* outc = outv + (size_t)4 * V * D;

    int sms = 148;
    cudaDeviceGetAttribute(&sms, cudaDevAttrMultiProcessorCount, 0);

    cudaFuncSetAttribute(mlp2seg_kernel,
                         cudaFuncAttributeMaxDynamicSharedMemorySize, MS_TOT);
    cudaFuncSetAttribute(update1_kernel,
                         cudaFuncAttributeMaxDynamicSharedMemorySize, US_TOT);

    // ---- prep (stream 0) ----
    {
        int mx = (V > C) ? V : C;
        zero_prep_kernel<<<(mx + NT - 1) / NT, NT>>>(V, C);
        int blk = (2 * Eh + NT - 1) / NT;
        degree_kernel<<<blk, NT>>>(v_edge, c_edge, p_edge, n_edge, Eh);
        scan4_kernel<<<4, 1024>>>(V, C);
        fill_kernel<<<blk, NT>>>(v_edge, c_edge, p_edge, n_edge, Eh);
        const int wtot = 4 * 2 * 128 * 128 + 2 * 384 * 128;
        wconv_all_kernel<<<(wtot + NT - 1) / NT, NT>>>(
            Wm[0], Wm[1], Wm[2], Wm[3], cuW, vuW);
        int etot = (V + C) * (D / 4);
        emb2h_kernel<<<(etot + NT - 1) / NT, NT>>>(v0, c0, V, C);
    }
    cudaMemcpyAsync(outv, v0, (size_t)V * D * sizeof(float), cudaMemcpyDeviceToDevice);
    cudaMemcpyAsync(outc, c0, (size_t)C * D * sizeof(float), cudaMemcpyDeviceToDevice);

    // ---- fork second stream (capture-legal) ----
    cudaStream_t s2;
    cudaStreamCreateWithFlags(&s2, cudaStreamNonBlocking);
    cudaEvent_t eFork, eC, eV;
    cudaEventCreateWithFlags(&eFork, cudaEventDisableTiming);
    cudaEventCreateWithFlags(&eC, cudaEventDisableTiming);
    cudaEventCreateWithFlags(&eV, cudaEventDisableTiming);
    cudaEventRecord(eFork, 0);
    cudaStreamWaitEvent(s2, eFork, 0);

    const int gblkC = (int)((2L * C * 16 + NT - 1) / NT);
    const int gblkV = (int)((2L * V * 16 + NT - 1) / NT);

    for (int t = 0; t < 3; t++) {
        const unsigned short* vinh = embh_v + (size_t)(t & 1) * VMAX * D;
        const unsigned short* cinh = embh_c + (size_t)(t & 1) * CMAX * D;
        unsigned short* vouth = embh_v + (size_t)((t + 1) & 1) * VMAX * D;
        unsigned short* couth = embh_c + (size_t)((t + 1) & 1) * CMAX * D;
        float* vout = outv + (size_t)(t + 1) * V * D;
        float* cout = outc + (size_t)(t + 1) * C * D;

        // cross-chain waits (bind to previous iteration's records)
        if (t > 0) {
            cudaStreamWaitEvent(s2, eC, 0);  // mlpC needs couth from updateC(t-1)
            cudaStreamWaitEvent(0, eV, 0);   // mlpV needs vouth from updateV(t-1)
        }

        // chain A (stream 0): mlpV -> gatherC -> updateC
        mlp2seg_kernel<<<2 * sms, NT, MS_TOT, 0>>>(
            vinh, (const uint4*)img_mlp, (const uint4*)(img_mlp + 2 * 32768),
            Bm[0], Bm[1], t_pv2c, t_nv2c, V);
        gather2_kernel<<<gblkC, NT, 0, 0>>>(
            t_pv2c, t_nv2c, agg_c_p, agg_c_n,
            rp_pc, sl_pc_s, sl_pc_w, rp_nc, sl_nc_s, sl_nc_w, C);
        update1_kernel<<<sms, NT, US_TOT, 0>>>(
            cinh, agg_c_p, agg_c_n, (const uint4*)img_cu, cub, cout, couth, C);
        cudaEventRecord(eC, 0);

        // chain B (stream s2): mlpC -> gatherV -> updateV
        mlp2seg_kernel<<<2 * sms, NT, MS_TOT, s2>>>(
            cinh, (const uint4*)(img_mlp + 4 * 32768),
            (const uint4*)(img_mlp + 6 * 32768),
            Bm[2], Bm[3], t_pc2v, t_nc2v, C);
        gather2_kernel<<<gblkV, NT, 0, s2>>>(
            t_pc2v, t_nc2v, agg_v_p, agg_v_n,
            rp_pv, sl_pv_s, sl_pv_w, rp_nv, sl_nv_s, sl_nv_w, V);
        update1_kernel<<<sms, NT, US_TOT, s2>>>(
            vinh, agg_v_p, agg_v_n, (const uint4*)img_vu, vub, vout, vouth, V);
        cudaEventRecord(eV, s2);
    }

    // join: stream 0 waits for chain B's final work (required to close capture)
    cudaStreamWaitEvent(0, eV, 0);
}